// round 2
// baseline (speedup 1.0000x reference)
#include <cuda_runtime.h>
#include <cuda_bf16.h>
#include <math.h>

// ---------------- problem constants ----------------
#define T_DIM 4096
#define S_DIM 4096
#define B_DIM 8
#define E_DIM 1024
#define BUCKET 16
#define NB 256            // T/BUCKET
#define TAU 0.75f
// SCALE = E^-0.5 = 1/32 ; alpha = SCALE/TAU
#define ATTN_ALPHA (1.0f/(32.0f*0.75f))

// ---------------- scratch (device globals; no allocation allowed) ----------------
__device__ float g_qm[B_DIM*NB*E_DIM];      // bucket-mean of query   (B,256,E) rows m=b*256+i
__device__ float g_km[B_DIM*NB*E_DIM];
__device__ float g_qb[B_DIM*NB*E_DIM];      // projected bucket queries
__device__ float g_kb[B_DIM*NB*E_DIM];
__device__ float g_la[B_DIM*NB*NB];         // sinkhorn logits / normalized
__device__ float g_p [B_DIM*NB*NB];         // exp(la)
__device__ float g_rowsum[B_DIM*NB];
__device__ int   g_kpmb[B_DIM*NB];
__device__ float g_wvo[E_DIM*E_DIM];        // Wo @ Wv  (row-major E x E)
__device__ float g_bvo[E_DIM];              // Wo @ bv
__device__ float g_z [T_DIM*B_DIM*E_DIM];   // mixed raw value, (T,B,E) layout

// ---------------- bucket mean: qm[b*256+i][e] = mean_pos X[(16i+pos),b,e] ----------------
__global__ void bucket_mean_kernel(const float* __restrict__ X, float* __restrict__ out) {
    int o = blockIdx.x * 256 + threadIdx.x;            // 2048*1024 total
    int e = o & (E_DIM - 1);
    int m = o >> 10;                                   // b*256+i
    int b = m >> 8;
    int i = m & 255;
    const float* src = X + (size_t)(i * BUCKET) * (B_DIM * E_DIM) + b * E_DIM + e;
    float s = 0.f;
#pragma unroll
    for (int pos = 0; pos < BUCKET; pos++) s += src[(size_t)pos * (B_DIM * E_DIM)];
    out[o] = s * (1.0f / BUCKET);
}

// ---------------- bucketed key-padding mask ----------------
__global__ void kpmb_kernel(const unsigned char* __restrict__ mask, int* __restrict__ kpmb) {
    int j = blockIdx.x * 256 + threadIdx.x;            // 2048
    if (j >= B_DIM * NB) return;
    int b = j >> 8, s = j & 255;
    const unsigned char* m = mask + b * S_DIM + s * BUCKET;
    int all = 1;
#pragma unroll
    for (int t = 0; t < BUCKET; t++) all &= (m[t] != 0);
    kpmb[j] = all;
}

__global__ void mask_kernel(float* __restrict__ la, const int* __restrict__ kpmb) {
    int idx = blockIdx.x * 256 + threadIdx.x;          // 8*256*256
    int b = idx >> 16, i = (idx >> 8) & 255, j = idx & 255;
    if (kpmb[b * 256 + i] != kpmb[b * 256 + j]) la[idx] = -1e30f;
}

// ---------------- bvo = Wo @ bv ----------------
__global__ void bvo_kernel(const float* __restrict__ Wo, const float* __restrict__ bv,
                           float* __restrict__ bvo) {
    int g = blockIdx.x * 8 + (threadIdx.x >> 5);       // one warp per output row
    int l = threadIdx.x & 31;
    if (g >= E_DIM) return;
    float s = 0.f;
    for (int k = l; k < E_DIM; k += 32) s += Wo[(size_t)g * E_DIM + k] * bv[k];
#pragma unroll
    for (int off = 16; off; off >>= 1) s += __shfl_xor_sync(0xffffffffu, s, off);
    if (l == 0) bvo[g] = s;
}

// ---------------- generic fp32 tiled GEMM: C[m,n] = alpha * sum_k A[m,k]*B'[n,k] (+bias) ----------------
// BTRANS=false: B row-major (N,K) ;  BTRANS=true: B row-major (K,N) (reads B[k*N+n])
// RS: C += rowsum(m)*bvo[n]   (final output GEMM only; m = t*8+b layout)
template <bool BTRANS, bool BIAS, bool RS>
__global__ __launch_bounds__(256, 2)
void gemm128_kernel(float* __restrict__ C, const float* __restrict__ A, const float* __restrict__ B,
                    const float* __restrict__ bias, const float* __restrict__ bvo,
                    const float* __restrict__ rowsum,
                    int M, int N, int K, float alpha,
                    long sA, long sB, long sC) {
    __shared__ float As[8][132];
    __shared__ float Bs[8][132];
    int z = blockIdx.z;
    A += (long)z * sA; B += (long)z * sB; C += (long)z * sC;
    int bm = blockIdx.y * 128, bn = blockIdx.x * 128;
    int tid = threadIdx.x, tx = tid & 15, ty = tid >> 4;
    float acc[8][8];
#pragma unroll
    for (int i = 0; i < 8; i++)
#pragma unroll
        for (int j = 0; j < 8; j++) acc[i][j] = 0.f;

    for (int k0 = 0; k0 < K; k0 += 8) {
        {   // A tile: As[k][m]
            int row = tid >> 1, part = tid & 1;
            float4 a4 = *(const float4*)(A + (size_t)(bm + row) * K + k0 + part * 4);
            As[part * 4 + 0][row] = a4.x; As[part * 4 + 1][row] = a4.y;
            As[part * 4 + 2][row] = a4.z; As[part * 4 + 3][row] = a4.w;
        }
        if (!BTRANS) {
            int row = tid >> 1, part = tid & 1;
            float4 b4 = *(const float4*)(B + (size_t)(bn + row) * K + k0 + part * 4);
            Bs[part * 4 + 0][row] = b4.x; Bs[part * 4 + 1][row] = b4.y;
            Bs[part * 4 + 2][row] = b4.z; Bs[part * 4 + 3][row] = b4.w;
        } else {
            int kk = tid >> 5, n4 = (tid & 31) * 4;
            *(float4*)&Bs[kk][n4] = *(const float4*)(B + (size_t)(k0 + kk) * N + bn + n4);
        }
        __syncthreads();
#pragma unroll
        for (int k = 0; k < 8; k++) {
            float4 a0 = *(float4*)&As[k][ty * 8];
            float4 a1 = *(float4*)&As[k][ty * 8 + 4];
            float4 b0 = *(float4*)&Bs[k][tx * 8];
            float4 b1 = *(float4*)&Bs[k][tx * 8 + 4];
            float ra[8] = {a0.x, a0.y, a0.z, a0.w, a1.x, a1.y, a1.z, a1.w};
            float rb[8] = {b0.x, b0.y, b0.z, b0.w, b1.x, b1.y, b1.z, b1.w};
#pragma unroll
            for (int i = 0; i < 8; i++)
#pragma unroll
                for (int j = 0; j < 8; j++) acc[i][j] = fmaf(ra[i], rb[j], acc[i][j]);
        }
        __syncthreads();
    }

#pragma unroll
    for (int i = 0; i < 8; i++) {
        int m = bm + ty * 8 + i;
        float rs = 0.f;
        if (RS) rs = rowsum[((m & 7) << 8) | (m >> 7)];   // b=m&7, tb=m>>7
        float out[8];
#pragma unroll
        for (int j = 0; j < 8; j++) {
            int n = bn + tx * 8 + j;
            float v = acc[i][j] * alpha;
            if (BIAS) v += bias[n];
            if (RS)   v += rs * bvo[n];
            out[j] = v;
        }
        float4* dst = (float4*)(C + (size_t)m * N + bn + tx * 8);
        dst[0] = make_float4(out[0], out[1], out[2], out[3]);
        dst[1] = make_float4(out[4], out[5], out[6], out[7]);
    }
}

// ---------------- fused sinkhorn: one block per batch, la in global (L2-resident) ----------------
__global__ __launch_bounds__(1024, 1)
void sinkhorn_kernel(float* __restrict__ la, float* __restrict__ p, float* __restrict__ rowsum) {
    int b = blockIdx.x;
    float* base = la + b * (NB * NB);
    int tid = threadIdx.x, w = tid >> 5, l = tid & 31;
    __shared__ float sh[32 * 256];
    __shared__ float colv[256];

    for (int it = 0; it < 8; it++) {
        // ---- row logsumexp (warp-local, rows w*8+ri, cols ci*32+l) ----
#pragma unroll
        for (int ri = 0; ri < 8; ri++) {
            int r = w * 8 + ri;
            float v[8];
#pragma unroll
            for (int ci = 0; ci < 8; ci++) v[ci] = base[r * 256 + ci * 32 + l];
            float m = v[0];
#pragma unroll
            for (int ci = 1; ci < 8; ci++) m = fmaxf(m, v[ci]);
#pragma unroll
            for (int off = 16; off; off >>= 1) m = fmaxf(m, __shfl_xor_sync(0xffffffffu, m, off));
            float s = 0.f;
#pragma unroll
            for (int ci = 0; ci < 8; ci++) s += __expf(v[ci] - m);
#pragma unroll
            for (int off = 16; off; off >>= 1) s += __shfl_xor_sync(0xffffffffu, s, off);
            float lse = m + __logf(s);
#pragma unroll
            for (int ci = 0; ci < 8; ci++) base[r * 256 + ci * 32 + l] = v[ci] - lse;
        }
        __syncthreads();
        // ---- column logsumexp ----
        float pm[8];
#pragma unroll
        for (int ci = 0; ci < 8; ci++) pm[ci] = -3.4e38f;
#pragma unroll
        for (int ri = 0; ri < 8; ri++)
#pragma unroll
            for (int ci = 0; ci < 8; ci++)
                pm[ci] = fmaxf(pm[ci], base[(w * 8 + ri) * 256 + ci * 32 + l]);
#pragma unroll
        for (int ci = 0; ci < 8; ci++) sh[w * 256 + ci * 32 + l] = pm[ci];
        __syncthreads();
        if (tid < 256) {
            float m = sh[tid];
#pragma unroll 4
            for (int ww = 1; ww < 32; ww++) m = fmaxf(m, sh[ww * 256 + tid]);
            colv[tid] = m;
        }
        __syncthreads();
        float ps[8];
#pragma unroll
        for (int ci = 0; ci < 8; ci++) ps[ci] = 0.f;
#pragma unroll
        for (int ri = 0; ri < 8; ri++)
#pragma unroll
            for (int ci = 0; ci < 8; ci++)
                ps[ci] += __expf(base[(w * 8 + ri) * 256 + ci * 32 + l] - colv[ci * 32 + l]);
#pragma unroll
        for (int ci = 0; ci < 8; ci++) sh[w * 256 + ci * 32 + l] = ps[ci];
        __syncthreads();
        if (tid < 256) {
            float s = 0.f;
#pragma unroll 4
            for (int ww = 0; ww < 32; ww++) s += sh[ww * 256 + tid];
            colv[tid] += __logf(s);
        }
        __syncthreads();
#pragma unroll
        for (int ri = 0; ri < 8; ri++)
#pragma unroll
            for (int ci = 0; ci < 8; ci++)
                base[(w * 8 + ri) * 256 + ci * 32 + l] -= colv[ci * 32 + l];
        __syncthreads();
    }

    // ---- p = exp(la), rowsum ----
#pragma unroll
    for (int ri = 0; ri < 8; ri++) {
        int r = w * 8 + ri;
        float s = 0.f;
#pragma unroll
        for (int ci = 0; ci < 8; ci++) {
            float e = __expf(base[r * 256 + ci * 32 + l]);
            p[b * (NB * NB) + r * 256 + ci * 32 + l] = e;
            s += e;
        }
#pragma unroll
        for (int off = 16; off; off >>= 1) s += __shfl_xor_sync(0xffffffffu, s, off);
        if (l == 0) rowsum[b * 256 + r] = s;
    }
}

// ---------------- bucket mix on RAW value: Z[t,b,e] = sum_s p[b,t/16,s] * value[16s + t%16, b, e] ----
// grid: (etile=16, pos=16, b=8); block 256; tile = 256 tb x 64 e
__global__ __launch_bounds__(256, 2)
void zmix_kernel(const float* __restrict__ value, const float* __restrict__ p, float* __restrict__ Z) {
    int et = blockIdx.x, pos = blockIdx.y, b = blockIdx.z;
    __shared__ float sp[16][256];
    __shared__ float sv[16][68];
    int tid = threadIdx.x, tx = tid & 15, ty = tid >> 4;
    float acc[16][4];
#pragma unroll
    for (int k = 0; k < 16; k++)
#pragma unroll
        for (int j = 0; j < 4; j++) acc[k][j] = 0.f;

    const float* pb = p + b * (NB * NB);
    for (int s0 = 0; s0 < 256; s0 += 16) {
        {   // sp[si][tb] = p[b][tb][s0+si] ; thread tid handles tb=tid
            const float4* src = (const float4*)(pb + (size_t)tid * 256 + s0);
#pragma unroll
            for (int q = 0; q < 4; q++) {
                float4 v = src[q];
                sp[q * 4 + 0][tid] = v.x; sp[q * 4 + 1][tid] = v.y;
                sp[q * 4 + 2][tid] = v.z; sp[q * 4 + 3][tid] = v.w;
            }
        }
        {   // sv[si][0..64) = value rows 16*(s0+si)+pos, cols et*64..
            int si = tid >> 4, j = tid & 15;
            float4 v = *(const float4*)(value +
                (size_t)((s0 + si) * BUCKET + pos) * (B_DIM * E_DIM) + b * E_DIM + et * 64 + j * 4);
            *(float4*)&sv[si][j * 4] = v;
        }
        __syncthreads();
#pragma unroll
        for (int si = 0; si < 16; si++) {
            float4 rv = *(float4*)&sv[si][tx * 4];
#pragma unroll
            for (int k = 0; k < 16; k++) {
                float a = sp[si][ty + (k << 4)];
                acc[k][0] = fmaf(a, rv.x, acc[k][0]);
                acc[k][1] = fmaf(a, rv.y, acc[k][1]);
                acc[k][2] = fmaf(a, rv.z, acc[k][2]);
                acc[k][3] = fmaf(a, rv.w, acc[k][3]);
            }
        }
        __syncthreads();
    }
#pragma unroll
    for (int k = 0; k < 16; k++) {
        int tb = k * 16 + ty;
        size_t off = (size_t)((tb * BUCKET + pos) * B_DIM + b) * E_DIM + et * 64 + tx * 4;
        *(float4*)(Z + off) = make_float4(acc[k][0], acc[k][1], acc[k][2], acc[k][3]);
    }
}

// ---------------- launch ----------------
extern "C" void kernel_launch(void* const* d_in, const int* in_sizes, int n_in,
                              void* d_out, int out_size) {
    const float* query = (const float*)d_in[0];
    const float* key_t = (const float*)d_in[1];
    const float* value = (const float*)d_in[2];
    const unsigned char* kpm = (const unsigned char*)d_in[3];
    const float* Wq = (const float*)d_in[4];
    const float* bq = (const float*)d_in[5];
    const float* Wk = (const float*)d_in[6];
    const float* bk = (const float*)d_in[7];
    const float* Wv = (const float*)d_in[8];
    const float* bv = (const float*)d_in[9];
    const float* Wo = (const float*)d_in[10];
    const float* bo = (const float*)d_in[11];
    float* out = (float*)d_out;

    float *qm, *km, *qb, *kb, *la, *p, *rowsum, *wvo, *bvo, *z;
    int* kpmb;
    cudaGetSymbolAddress((void**)&qm, g_qm);
    cudaGetSymbolAddress((void**)&km, g_km);
    cudaGetSymbolAddress((void**)&qb, g_qb);
    cudaGetSymbolAddress((void**)&kb, g_kb);
    cudaGetSymbolAddress((void**)&la, g_la);
    cudaGetSymbolAddress((void**)&p, g_p);
    cudaGetSymbolAddress((void**)&rowsum, g_rowsum);
    cudaGetSymbolAddress((void**)&kpmb, g_kpmb);
    cudaGetSymbolAddress((void**)&wvo, g_wvo);
    cudaGetSymbolAddress((void**)&bvo, g_bvo);
    cudaGetSymbolAddress((void**)&z, g_z);

    // 1) bucket means of raw query/key
    bucket_mean_kernel<<<(B_DIM * NB * E_DIM) / 256, 256>>>(query, qm);
    bucket_mean_kernel<<<(B_DIM * NB * E_DIM) / 256, 256>>>(key_t, km);

    // 2) project bucket means: qb = qm @ Wq^T + bq ; kb = km @ Wk^T + bk   (M=2048,N=1024,K=1024)
    gemm128_kernel<false, true, false><<<dim3(8, 16, 1), 256>>>(
        qb, qm, Wq, bq, nullptr, nullptr, 2048, 1024, 1024, 1.0f, 0, 0, 0);
    gemm128_kernel<false, true, false><<<dim3(8, 16, 1), 256>>>(
        kb, km, Wk, bk, nullptr, nullptr, 2048, 1024, 1024, 1.0f, 0, 0, 0);

    // 3) fold Wv into Wo:  wvo = Wo @ Wv  (reads Wv as (K,N)) ; bvo = Wo @ bv
    gemm128_kernel<true, false, false><<<dim3(8, 8, 1), 256>>>(
        wvo, Wo, Wv, nullptr, nullptr, nullptr, 1024, 1024, 1024, 1.0f, 0, 0, 0);
    bvo_kernel<<<128, 256>>>(Wo, bv, bvo);

    // 4) attn logits: la[b,i,j] = (qb . kb) * SCALE / TAU  (batched, M=N=256, K=1024)
    gemm128_kernel<false, false, false><<<dim3(2, 2, B_DIM), 256>>>(
        la, qb, kb, nullptr, nullptr, nullptr, 256, 256, 1024, ATTN_ALPHA,
        (long)NB * E_DIM, (long)NB * E_DIM, (long)NB * NB);

    // 5) mask
    kpmb_kernel<<<8, 256>>>(kpm, kpmb);
    mask_kernel<<<(B_DIM * NB * NB) / 256, 256>>>(la, kpmb);

    // 6) sinkhorn (8 iters) -> p, rowsum
    sinkhorn_kernel<<<B_DIM, 1024>>>(la, p, rowsum);

    // 7) bucket mix on raw value -> Z (T,B,E)
    zmix_kernel<<<dim3(16, 16, B_DIM), 256>>>(value, p, z);

    // 8) final: out = Z @ wvo^T + rowsum*bvo + bo  (M=32768,N=1024,K=1024)
    gemm128_kernel<false, true, true><<<dim3(8, 256, 1), 256>>>(
        out, z, wvo, bo, bvo, rowsum, 32768, 1024, 1024, 1.0f, 0, 0, 0);
}

// round 4
// speedup vs baseline: 1.4605x; 1.4605x over previous
#include <cuda_runtime.h>
#include <cuda_bf16.h>
#include <math.h>
#include <cstdint>

// ---------------- problem constants ----------------
#define T_DIM 4096
#define S_DIM 4096
#define B_DIM 8
#define E_DIM 1024
#define BUCKET 16
#define NB 256            // T/BUCKET
#define TAU 0.75f
#define ATTN_ALPHA (1.0f/(32.0f*0.75f))

// ---------------- scratch (device globals; no allocation allowed) ----------------
__device__ float g_qm[B_DIM*NB*E_DIM];
__device__ float g_km[B_DIM*NB*E_DIM];
__device__ float g_qb[B_DIM*NB*E_DIM];
__device__ float g_kb[B_DIM*NB*E_DIM];
__device__ float g_la[B_DIM*NB*NB];
__device__ float g_p [B_DIM*NB*NB];
__device__ float g_rowsum[B_DIM*NB];
__device__ int   g_kpmb[B_DIM*NB];
__device__ float g_wvo[E_DIM*E_DIM];        // Wo @ Wv  (row-major E x E)
__device__ float g_bvo[E_DIM];              // Wo @ bv
__device__ __nv_bfloat16 g_zhi[T_DIM*B_DIM*E_DIM];   // Z split hi (rows m=t*8+b, 1024 cols)
__device__ __nv_bfloat16 g_zlo[T_DIM*B_DIM*E_DIM];
__device__ __nv_bfloat16 g_wvoh[E_DIM*E_DIM];
__device__ __nv_bfloat16 g_wvol[E_DIM*E_DIM];

// =================== warp-MMA helpers (compute_80-compatible PTX) ===================
__device__ __forceinline__ uint32_t smem_u32(const void* p) {
    uint32_t a;
    asm("{ .reg .u64 t; cvta.to.shared.u64 t, %1; cvt.u32.u64 %0, t; }" : "=r"(a) : "l"(p));
    return a;
}

#define CP_ASYNC16(dst, src) \
    asm volatile("cp.async.cg.shared.global [%0], [%1], 16;" :: "r"(dst), "l"(src))
#define CP_COMMIT() asm volatile("cp.async.commit_group;")
#define CP_WAIT1()  asm volatile("cp.async.wait_group 1;")
#define CP_WAIT0()  asm volatile("cp.async.wait_group 0;")

#define LDSM_X4(r0, r1, r2, r3, addr) \
    asm volatile("ldmatrix.sync.aligned.m8n8.x4.shared.b16 {%0,%1,%2,%3}, [%4];" \
        : "=r"(r0), "=r"(r1), "=r"(r2), "=r"(r3) : "r"(addr))

#define MMA16816(d, a0, a1, a2, a3, b0, b1) \
    asm volatile("mma.sync.aligned.m16n8k16.row.col.f32.bf16.bf16.f32 " \
        "{%0,%1,%2,%3}, {%4,%5,%6,%7}, {%8,%9}, {%0,%1,%2,%3};" \
        : "+f"((d)[0]), "+f"((d)[1]), "+f"((d)[2]), "+f"((d)[3]) \
        : "r"(a0), "r"(a1), "r"(a2), "r"(a3), "r"(b0), "r"(b1))

// =================== final GEMM: out = Zhi*Whi' + Zhi*Wlo' + Zlo*Whi' + bias ===================
// CTA tile 128(M) x 128(N), warp grid 2x4, warp tile 64x32, KC=32, double-buffered cp.async.
#define KC 32
#define ROW_B 80                     // bf16 row stride in bytes (32*2 + 16 pad)
#define TILE_B (128*ROW_B)           // 10240 B per sub-tile (Ahi/Alo/Bhi/Blo)
#define STAGE_B (4*TILE_B)           // 40960 B per stage
#define HMMA_SMEM (2*STAGE_B)        // 81920 B

__global__ __launch_bounds__(256, 1)
void hmma_out_kernel(float* __restrict__ out,
                     const __nv_bfloat16* __restrict__ Ahi, const __nv_bfloat16* __restrict__ Alo,
                     const __nv_bfloat16* __restrict__ Bhi, const __nv_bfloat16* __restrict__ Blo,
                     const float* __restrict__ bo, const float* __restrict__ bvo,
                     const float* __restrict__ rowsum) {
    extern __shared__ char smem[];
    uint32_t sbase = smem_u32(smem);

    int tid = threadIdx.x, wid = tid >> 5, lane = tid & 31;
    int bm = blockIdx.y * 128, bn = blockIdx.x * 128;
    int wm = (wid & 1) * 64, wn = (wid >> 1) * 32;

    const __nv_bfloat16* gsrc[4] = {
        Ahi + (size_t)bm * 1024, Alo + (size_t)bm * 1024,
        Bhi + (size_t)bn * 1024, Blo + (size_t)bn * 1024 };

    float acc[4][4][4];
#pragma unroll
    for (int i = 0; i < 4; i++)
#pragma unroll
        for (int j = 0; j < 4; j++)
#pragma unroll
            for (int r = 0; r < 4; r++) acc[i][j][r] = 0.f;

    auto stage_load = [&](int kt, int buf) {
        int k0 = kt * KC;
        uint32_t base = sbase + buf * STAGE_B;
#pragma unroll
        for (int tile = 0; tile < 4; tile++) {
            const __nv_bfloat16* g = gsrc[tile];
#pragma unroll
            for (int q = 0; q < 2; q++) {
                int c = tid + q * 256;            // 512 16B-chunks per sub-tile
                int row = c >> 2, seg = c & 3;
                uint32_t dst = base + tile * TILE_B + row * ROW_B + seg * 16;
                CP_ASYNC16(dst, g + (size_t)row * 1024 + k0 + seg * 8);
            }
        }
        CP_COMMIT();
    };

    // ldmatrix source addresses (per-thread, fixed except buffer/ks offsets)
    int lrow = lane & 15, lkseg = (lane >> 4) * 8;   // 0 or 8 elements

    stage_load(0, 0);

    const int NKT = 1024 / KC;   // 32
    for (int kt = 0; kt < NKT; kt++) {
        int buf = kt & 1;
        if (kt + 1 < NKT) { stage_load(kt + 1, buf ^ 1); CP_WAIT1(); }
        else             { CP_WAIT0(); }
        __syncthreads();

        uint32_t base = sbase + buf * STAGE_B;
        uint32_t aH = base + 0 * TILE_B, aL = base + 1 * TILE_B;
        uint32_t bH = base + 2 * TILE_B, bL = base + 3 * TILE_B;

#pragma unroll
        for (int ks = 0; ks < KC / 16; ks++) {
            int kb = (ks * 16 + lkseg) * 2;   // byte offset in row
            uint32_t ah[4][4], al[4][4], bh[2][4], bl[2][4];
#pragma unroll
            for (int mt = 0; mt < 4; mt++) {
                uint32_t off = (wm + mt * 16 + lrow) * ROW_B + kb;
                LDSM_X4(ah[mt][0], ah[mt][1], ah[mt][2], ah[mt][3], aH + off);
                LDSM_X4(al[mt][0], al[mt][1], al[mt][2], al[mt][3], aL + off);
            }
#pragma unroll
            for (int nt = 0; nt < 2; nt++) {
                uint32_t off = (wn + nt * 16 + lrow) * ROW_B + kb;
                LDSM_X4(bh[nt][0], bh[nt][1], bh[nt][2], bh[nt][3], bH + off);
                LDSM_X4(bl[nt][0], bl[nt][1], bl[nt][2], bl[nt][3], bL + off);
            }
#pragma unroll
            for (int mt = 0; mt < 4; mt++) {
#pragma unroll
                for (int j = 0; j < 4; j++) {
                    int nt = j >> 1, hi = j & 1;   // n8 tile j: regs {r0,r2} or {r1,r3}
                    uint32_t b0h = bh[nt][hi], b1h = bh[nt][hi + 2];
                    uint32_t b0l = bl[nt][hi], b1l = bl[nt][hi + 2];
                    MMA16816(acc[mt][j], ah[mt][0], ah[mt][1], ah[mt][2], ah[mt][3], b0h, b1h);
                    MMA16816(acc[mt][j], ah[mt][0], ah[mt][1], ah[mt][2], ah[mt][3], b0l, b1l);
                    MMA16816(acc[mt][j], al[mt][0], al[mt][1], al[mt][2], al[mt][3], b0h, b1h);
                }
            }
        }
        __syncthreads();
    }

    // ---- epilogue ----
#pragma unroll
    for (int mt = 0; mt < 4; mt++) {
        int m0 = bm + wm + mt * 16 + (lane >> 2);
        int m1 = m0 + 8;
        float rs0 = rowsum[((m0 & 7) << 8) | (m0 >> 7)];
        float rs1 = rowsum[((m1 & 7) << 8) | (m1 >> 7)];
#pragma unroll
        for (int j = 0; j < 4; j++) {
            int n = bn + wn + j * 8 + (lane & 3) * 2;
            float bb0 = bo[n]     + rs0 * bvo[n];
            float bb1 = bo[n + 1] + rs0 * bvo[n + 1];
            float cb0 = bo[n]     + rs1 * bvo[n];
            float cb1 = bo[n + 1] + rs1 * bvo[n + 1];
            *(float2*)(out + (size_t)m0 * 1024 + n) = make_float2(acc[mt][j][0] + bb0, acc[mt][j][1] + bb1);
            *(float2*)(out + (size_t)m1 * 1024 + n) = make_float2(acc[mt][j][2] + cb0, acc[mt][j][3] + cb1);
        }
    }
}

// =================== elementwise / small kernels ===================
__global__ void bucket_mean_kernel(const float* __restrict__ X, float* __restrict__ out) {
    int o = blockIdx.x * 256 + threadIdx.x;
    int e = o & (E_DIM - 1);
    int m = o >> 10;
    int b = m >> 8;
    int i = m & 255;
    const float* src = X + (size_t)(i * BUCKET) * (B_DIM * E_DIM) + b * E_DIM + e;
    float s = 0.f;
#pragma unroll
    for (int pos = 0; pos < BUCKET; pos++) s += src[(size_t)pos * (B_DIM * E_DIM)];
    out[o] = s * (1.0f / BUCKET);
}

__global__ void kpmb_kernel(const unsigned char* __restrict__ mask, int* __restrict__ kpmb) {
    int j = blockIdx.x * 256 + threadIdx.x;
    if (j >= B_DIM * NB) return;
    int b = j >> 8, s = j & 255;
    const unsigned char* m = mask + b * S_DIM + s * BUCKET;
    int all = 1;
#pragma unroll
    for (int t = 0; t < BUCKET; t++) all &= (m[t] != 0);
    kpmb[j] = all;
}

__global__ void mask_kernel(float* __restrict__ la, const int* __restrict__ kpmb) {
    int idx = blockIdx.x * 256 + threadIdx.x;
    int b = idx >> 16, i = (idx >> 8) & 255, j = idx & 255;
    if (kpmb[b * 256 + i] != kpmb[b * 256 + j]) la[idx] = -1e30f;
}

__global__ void bvo_kernel(const float* __restrict__ Wo, const float* __restrict__ bv,
                           float* __restrict__ bvo) {
    int g = blockIdx.x * 8 + (threadIdx.x >> 5);
    int l = threadIdx.x & 31;
    if (g >= E_DIM) return;
    float s = 0.f;
    for (int k = l; k < E_DIM; k += 32) s += Wo[(size_t)g * E_DIM + k] * bv[k];
#pragma unroll
    for (int off = 16; off; off >>= 1) s += __shfl_xor_sync(0xffffffffu, s, off);
    if (l == 0) bvo[g] = s;
}

__global__ void split_kernel(const float* __restrict__ X, __nv_bfloat16* __restrict__ hi,
                             __nv_bfloat16* __restrict__ lo, int n) {
    int i = blockIdx.x * 256 + threadIdx.x;
    if (i >= n) return;
    float v = X[i];
    __nv_bfloat16 h = __float2bfloat16_rn(v);
    hi[i] = h;
    lo[i] = __float2bfloat16_rn(v - __bfloat162float(h));
}

// ---------------- generic fp32 tiled GEMM (projections / attn / wvo) ----------------
template <bool BTRANS, bool BIAS>
__global__ __launch_bounds__(256, 2)
void gemm128_kernel(float* __restrict__ C, const float* __restrict__ A, const float* __restrict__ B,
                    const float* __restrict__ bias,
                    int M, int N, int K, float alpha,
                    long sA, long sB, long sC) {
    __shared__ float As[8][132];
    __shared__ float Bs[8][132];
    int z = blockIdx.z;
    A += (long)z * sA; B += (long)z * sB; C += (long)z * sC;
    int bm = blockIdx.y * 128, bn = blockIdx.x * 128;
    int tid = threadIdx.x, tx = tid & 15, ty = tid >> 4;
    float acc[8][8];
#pragma unroll
    for (int i = 0; i < 8; i++)
#pragma unroll
        for (int j = 0; j < 8; j++) acc[i][j] = 0.f;

    for (int k0 = 0; k0 < K; k0 += 8) {
        {
            int row = tid >> 1, part = tid & 1;
            float4 a4 = *(const float4*)(A + (size_t)(bm + row) * K + k0 + part * 4);
            As[part * 4 + 0][row] = a4.x; As[part * 4 + 1][row] = a4.y;
            As[part * 4 + 2][row] = a4.z; As[part * 4 + 3][row] = a4.w;
        }
        if (!BTRANS) {
            int row = tid >> 1, part = tid & 1;
            float4 b4 = *(const float4*)(B + (size_t)(bn + row) * K + k0 + part * 4);
            Bs[part * 4 + 0][row] = b4.x; Bs[part * 4 + 1][row] = b4.y;
            Bs[part * 4 + 2][row] = b4.z; Bs[part * 4 + 3][row] = b4.w;
        } else {
            int kk = tid >> 5, n4 = (tid & 31) * 4;
            *(float4*)&Bs[kk][n4] = *(const float4*)(B + (size_t)(k0 + kk) * N + bn + n4);
        }
        __syncthreads();
#pragma unroll
        for (int k = 0; k < 8; k++) {
            float4 a0 = *(float4*)&As[k][ty * 8];
            float4 a1 = *(float4*)&As[k][ty * 8 + 4];
            float4 b0 = *(float4*)&Bs[k][tx * 8];
            float4 b1 = *(float4*)&Bs[k][tx * 8 + 4];
            float ra[8] = {a0.x, a0.y, a0.z, a0.w, a1.x, a1.y, a1.z, a1.w};
            float rb[8] = {b0.x, b0.y, b0.z, b0.w, b1.x, b1.y, b1.z, b1.w};
#pragma unroll
            for (int i = 0; i < 8; i++)
#pragma unroll
                for (int j = 0; j < 8; j++) acc[i][j] = fmaf(ra[i], rb[j], acc[i][j]);
        }
        __syncthreads();
    }

#pragma unroll
    for (int i = 0; i < 8; i++) {
        int m = bm + ty * 8 + i;
        float o[8];
#pragma unroll
        for (int j = 0; j < 8; j++) {
            int n = bn + tx * 8 + j;
            float v = acc[i][j] * alpha;
            if (BIAS) v += bias[n];
            o[j] = v;
        }
        float4* dst = (float4*)(C + (size_t)m * N + bn + tx * 8);
        dst[0] = make_float4(o[0], o[1], o[2], o[3]);
        dst[1] = make_float4(o[4], o[5], o[6], o[7]);
    }
}

// ---------------- fused sinkhorn ----------------
__global__ __launch_bounds__(1024, 1)
void sinkhorn_kernel(float* __restrict__ la, float* __restrict__ p, float* __restrict__ rowsum) {
    int b = blockIdx.x;
    float* base = la + b * (NB * NB);
    int tid = threadIdx.x, w = tid >> 5, l = tid & 31;
    __shared__ float sh[32 * 256];
    __shared__ float colv[256];

    for (int it = 0; it < 8; it++) {
#pragma unroll
        for (int ri = 0; ri < 8; ri++) {
            int r = w * 8 + ri;
            float v[8];
#pragma unroll
            for (int ci = 0; ci < 8; ci++) v[ci] = base[r * 256 + ci * 32 + l];
            float m = v[0];
#pragma unroll
            for (int ci = 1; ci < 8; ci++) m = fmaxf(m, v[ci]);
#pragma unroll
            for (int off = 16; off; off >>= 1) m = fmaxf(m, __shfl_xor_sync(0xffffffffu, m, off));
            float s = 0.f;
#pragma unroll
            for (int ci = 0; ci < 8; ci++) s += __expf(v[ci] - m);
#pragma unroll
            for (int off = 16; off; off >>= 1) s += __shfl_xor_sync(0xffffffffu, s, off);
            float lse = m + __logf(s);
#pragma unroll
            for (int ci = 0; ci < 8; ci++) base[r * 256 + ci * 32 + l] = v[ci] - lse;
        }
        __syncthreads();
        float pm[8];
#pragma unroll
        for (int ci = 0; ci < 8; ci++) pm[ci] = -3.4e38f;
#pragma unroll
        for (int ri = 0; ri < 8; ri++)
#pragma unroll
            for (int ci = 0; ci < 8; ci++)
                pm[ci] = fmaxf(pm[ci], base[(w * 8 + ri) * 256 + ci * 32 + l]);
#pragma unroll
        for (int ci = 0; ci < 8; ci++) sh[w * 256 + ci * 32 + l] = pm[ci];
        __syncthreads();
        if (tid < 256) {
            float m = sh[tid];
#pragma unroll 4
            for (int ww = 1; ww < 32; ww++) m = fmaxf(m, sh[ww * 256 + tid]);
            colv[tid] = m;
        }
        __syncthreads();
        float ps[8];
#pragma unroll
        for (int ci = 0; ci < 8; ci++) ps[ci] = 0.f;
#pragma unroll
        for (int ri = 0; ri < 8; ri++)
#pragma unroll
            for (int ci = 0; ci < 8; ci++)
                ps[ci] += __expf(base[(w * 8 + ri) * 256 + ci * 32 + l] - colv[ci * 32 + l]);
#pragma unroll
        for (int ci = 0; ci < 8; ci++) sh[w * 256 + ci * 32 + l] = ps[ci];
        __syncthreads();
        if (tid < 256) {
            float s = 0.f;
#pragma unroll 4
            for (int ww = 0; ww < 32; ww++) s += sh[ww * 256 + tid];
            colv[tid] += __logf(s);
        }
        __syncthreads();
#pragma unroll
        for (int ri = 0; ri < 8; ri++)
#pragma unroll
            for (int ci = 0; ci < 8; ci++)
                base[(w * 8 + ri) * 256 + ci * 32 + l] -= colv[ci * 32 + l];
        __syncthreads();
    }

#pragma unroll
    for (int ri = 0; ri < 8; ri++) {
        int r = w * 8 + ri;
        float s = 0.f;
#pragma unroll
        for (int ci = 0; ci < 8; ci++) {
            float e = __expf(base[r * 256 + ci * 32 + l]);
            p[b * (NB * NB) + r * 256 + ci * 32 + l] = e;
            s += e;
        }
#pragma unroll
        for (int off = 16; off; off >>= 1) s += __shfl_xor_sync(0xffffffffu, s, off);
        if (l == 0) rowsum[b * 256 + r] = s;
    }
}

// ---------------- bucket mix on RAW value -> split bf16 Z ----------------
__global__ __launch_bounds__(256, 2)
void zmix_kernel(const float* __restrict__ value, const float* __restrict__ p,
                 __nv_bfloat16* __restrict__ Zhi, __nv_bfloat16* __restrict__ Zlo) {
    int et = blockIdx.x, pos = blockIdx.y, b = blockIdx.z;
    __shared__ float sp[16][256];
    __shared__ float sv[16][68];
    int tid = threadIdx.x, tx = tid & 15, ty = tid >> 4;
    float acc[16][4];
#pragma unroll
    for (int k = 0; k < 16; k++)
#pragma unroll
        for (int j = 0; j < 4; j++) acc[k][j] = 0.f;

    const float* pb = p + b * (NB * NB);
    for (int s0 = 0; s0 < 256; s0 += 16) {
        {
            const float4* src = (const float4*)(pb + (size_t)tid * 256 + s0);
#pragma unroll
            for (int q = 0; q < 4; q++) {
                float4 v = src[q];
                sp[q * 4 + 0][tid] = v.x; sp[q * 4 + 1][tid] = v.y;
                sp[q * 4 + 2][tid] = v.z; sp[q * 4 + 3][tid] = v.w;
            }
        }
        {
            int si = tid >> 4, j = tid & 15;
            float4 v = *(const float4*)(value +
                (size_t)((s0 + si) * BUCKET + pos) * (B_DIM * E_DIM) + b * E_DIM + et * 64 + j * 4);
            *(float4*)&sv[si][j * 4] = v;
        }
        __syncthreads();
#pragma unroll
        for (int si = 0; si < 16; si++) {
            float4 rv = *(float4*)&sv[si][tx * 4];
#pragma unroll
            for (int k = 0; k < 16; k++) {
                float a = sp[si][ty + (k << 4)];
                acc[k][0] = fmaf(a, rv.x, acc[k][0]);
                acc[k][1] = fmaf(a, rv.y, acc[k][1]);
                acc[k][2] = fmaf(a, rv.z, acc[k][2]);
                acc[k][3] = fmaf(a, rv.w, acc[k][3]);
            }
        }
        __syncthreads();
    }
#pragma unroll
    for (int k = 0; k < 16; k++) {
        int tb = k * 16 + ty;
        size_t off = (size_t)((tb * BUCKET + pos) * B_DIM + b) * E_DIM + et * 64 + tx * 4;
        __nv_bfloat16 h[4], lo[4];
#pragma unroll
        for (int j = 0; j < 4; j++) {
            float v = acc[k][j];
            h[j] = __float2bfloat16_rn(v);
            lo[j] = __float2bfloat16_rn(v - __bfloat162float(h[j]));
        }
        *(uint2*)(Zhi + off) = *(uint2*)h;
        *(uint2*)(Zlo + off) = *(uint2*)lo;
    }
}

// ---------------- launch ----------------
extern "C" void kernel_launch(void* const* d_in, const int* in_sizes, int n_in,
                              void* d_out, int out_size) {
    const float* query = (const float*)d_in[0];
    const float* key_t = (const float*)d_in[1];
    const float* value = (const float*)d_in[2];
    const unsigned char* kpm = (const unsigned char*)d_in[3];
    const float* Wq = (const float*)d_in[4];
    const float* bq = (const float*)d_in[5];
    const float* Wk = (const float*)d_in[6];
    const float* bk = (const float*)d_in[7];
    const float* Wv = (const float*)d_in[8];
    const float* bv = (const float*)d_in[9];
    const float* Wo = (const float*)d_in[10];
    const float* bo = (const float*)d_in[11];
    float* out = (float*)d_out;

    float *qm, *km, *qb, *kb, *la, *p, *rowsum, *wvo, *bvo;
    __nv_bfloat16 *zhi, *zlo, *wvoh, *wvol;
    int* kpmb;
    cudaGetSymbolAddress((void**)&qm, g_qm);
    cudaGetSymbolAddress((void**)&km, g_km);
    cudaGetSymbolAddress((void**)&qb, g_qb);
    cudaGetSymbolAddress((void**)&kb, g_kb);
    cudaGetSymbolAddress((void**)&la, g_la);
    cudaGetSymbolAddress((void**)&p, g_p);
    cudaGetSymbolAddress((void**)&rowsum, g_rowsum);
    cudaGetSymbolAddress((void**)&kpmb, g_kpmb);
    cudaGetSymbolAddress((void**)&wvo, g_wvo);
    cudaGetSymbolAddress((void**)&bvo, g_bvo);
    cudaGetSymbolAddress((void**)&zhi, g_zhi);
    cudaGetSymbolAddress((void**)&zlo, g_zlo);
    cudaGetSymbolAddress((void**)&wvoh, g_wvoh);
    cudaGetSymbolAddress((void**)&wvol, g_wvol);

    static bool attr_set = false;
    if (!attr_set) {
        cudaFuncSetAttribute(hmma_out_kernel, cudaFuncAttributeMaxDynamicSharedMemorySize, HMMA_SMEM);
        attr_set = true;
    }

    // 1) bucket means of raw query/key
    bucket_mean_kernel<<<(B_DIM * NB * E_DIM) / 256, 256>>>(query, qm);
    bucket_mean_kernel<<<(B_DIM * NB * E_DIM) / 256, 256>>>(key_t, km);

    // 2) project bucket means
    gemm128_kernel<false, true><<<dim3(8, 16, 1), 256>>>(
        qb, qm, Wq, bq, 2048, 1024, 1024, 1.0f, 0, 0, 0);
    gemm128_kernel<false, true><<<dim3(8, 16, 1), 256>>>(
        kb, km, Wk, bk, 2048, 1024, 1024, 1.0f, 0, 0, 0);

    // 3) fold Wv into Wo, split to bf16 hi/lo; bvo = Wo @ bv
    gemm128_kernel<true, false><<<dim3(8, 8, 1), 256>>>(
        wvo, Wo, Wv, nullptr, 1024, 1024, 1024, 1.0f, 0, 0, 0);
    split_kernel<<<(E_DIM * E_DIM) / 256, 256>>>(wvo, wvoh, wvol, E_DIM * E_DIM);
    bvo_kernel<<<128, 256>>>(Wo, bv, bvo);

    // 4) attn logits
    gemm128_kernel<false, false><<<dim3(2, 2, B_DIM), 256>>>(
        la, qb, kb, nullptr, 256, 256, 1024, ATTN_ALPHA,
        (long)NB * E_DIM, (long)NB * E_DIM, (long)NB * NB);

    // 5) mask
    kpmb_kernel<<<8, 256>>>(kpm, kpmb);
    mask_kernel<<<(B_DIM * NB * NB) / 256, 256>>>(la, kpmb);

    // 6) sinkhorn
    sinkhorn_kernel<<<B_DIM, 1024>>>(la, p, rowsum);

    // 7) bucket mix -> split bf16 Z
    zmix_kernel<<<dim3(16, 16, B_DIM), 256>>>(value, p, zhi, zlo);

    // 8) final: warp-MMA split-bf16 GEMM (M=32768, N=1024, K=1024)
    hmma_out_kernel<<<dim3(8, 256, 1), 256, HMMA_SMEM>>>(
        out, zhi, zlo, wvoh, wvol, bo, bvo, rowsum);
}

// round 5
// speedup vs baseline: 1.8233x; 1.2484x over previous
#include <cuda_runtime.h>
#include <cuda_bf16.h>
#include <cuda_fp16.h>
#include <math.h>
#include <cstdint>

// ---------------- problem constants ----------------
#define T_DIM 4096
#define S_DIM 4096
#define B_DIM 8
#define E_DIM 1024
#define BUCKET 16
#define NB 256            // T/BUCKET
#define TAU 0.75f
#define ATTN_ALPHA (1.0f/(32.0f*0.75f))

// ---------------- scratch (device globals; no allocation allowed) ----------------
__device__ float g_qm[B_DIM*NB*E_DIM];
__device__ float g_km[B_DIM*NB*E_DIM];
__device__ float g_qb[B_DIM*NB*E_DIM];
__device__ float g_kb[B_DIM*NB*E_DIM];
__device__ float g_la[B_DIM*NB*NB];
__device__ float g_p [B_DIM*NB*NB];
__device__ float g_rowsum[B_DIM*NB];
__device__ int   g_kpmb[B_DIM*NB];
__device__ float g_wvo[E_DIM*E_DIM];        // Wo @ Wv  (row-major E x E)
__device__ float g_bvo[E_DIM];              // Wo @ bv
__device__ __half g_zh[T_DIM*B_DIM*E_DIM];  // mixed value, fp16 (rows m=t*8+b, 1024 cols)
__device__ __half g_wvoh[E_DIM*E_DIM];      // wvo in fp16

// =================== warp-MMA helpers (compute_80-compatible PTX) ===================
__device__ __forceinline__ uint32_t smem_u32(const void* p) {
    uint32_t a;
    asm("{ .reg .u64 t; cvta.to.shared.u64 t, %1; cvt.u32.u64 %0, t; }" : "=r"(a) : "l"(p));
    return a;
}

#define CP_ASYNC16(dst, src) \
    asm volatile("cp.async.cg.shared.global [%0], [%1], 16;" :: "r"(dst), "l"(src))
#define CP_COMMIT() asm volatile("cp.async.commit_group;")
#define CP_WAIT3()  asm volatile("cp.async.wait_group 3;")

#define LDSM_X4(r0, r1, r2, r3, addr) \
    asm volatile("ldmatrix.sync.aligned.m8n8.x4.shared.b16 {%0,%1,%2,%3}, [%4];" \
        : "=r"(r0), "=r"(r1), "=r"(r2), "=r"(r3) : "r"(addr))

#define MMA16816F16(d, a0, a1, a2, a3, b0, b1) \
    asm volatile("mma.sync.aligned.m16n8k16.row.col.f32.f16.f16.f32 " \
        "{%0,%1,%2,%3}, {%4,%5,%6,%7}, {%8,%9}, {%0,%1,%2,%3};" \
        : "+f"((d)[0]), "+f"((d)[1]), "+f"((d)[2]), "+f"((d)[3]) \
        : "r"(a0), "r"(a1), "r"(a2), "r"(a3), "r"(b0), "r"(b1))

// =================== final GEMM: out = Zh*Wh' + bo + rowsum*bvo ===================
// CTA tile 128(M) x 256(N), warps 2x4 (warp tile 64x64), KC=32, 4-stage cp.async.
#define KC 32
#define ROW_B 80                      // fp16 row stride in bytes (32*2 + 16 pad, conflict-free ldmatrix)
#define A_TILE_B (128*ROW_B)          // 10240
#define B_TILE_B (256*ROW_B)          // 20480
#define STAGE_B (A_TILE_B + B_TILE_B) // 30720
#define HMMA_SMEM (4*STAGE_B)         // 122880

__global__ __launch_bounds__(256, 1)
void hmma_out_kernel(float* __restrict__ out,
                     const __half* __restrict__ Ah, const __half* __restrict__ Bh,
                     const float* __restrict__ bo, const float* __restrict__ bvo,
                     const float* __restrict__ rowsum) {
    extern __shared__ char smem[];
    uint32_t sbase = smem_u32(smem);

    int tid = threadIdx.x, wid = tid >> 5, lane = tid & 31;
    int bm = blockIdx.y * 128, bn = blockIdx.x * 256;
    int wm = (wid & 1) * 64, wn = (wid >> 1) * 64;

    const __half* Ag = Ah + (size_t)bm * 1024;
    const __half* Bg = Bh + (size_t)bn * 1024;

    float acc[4][8][4];
#pragma unroll
    for (int i = 0; i < 4; i++)
#pragma unroll
        for (int j = 0; j < 8; j++)
#pragma unroll
            for (int r = 0; r < 4; r++) acc[i][j][r] = 0.f;

    auto stage_load = [&](int kt, int buf) {
        int k0 = kt * KC;
        uint32_t base = sbase + buf * STAGE_B;
#pragma unroll
        for (int q = 0; q < 2; q++) {           // A: 512 chunks
            int c = tid + q * 256;
            int row = c >> 2, seg = c & 3;
            CP_ASYNC16(base + row * ROW_B + seg * 16,
                       Ag + (size_t)row * 1024 + k0 + seg * 8);
        }
#pragma unroll
        for (int q = 0; q < 4; q++) {           // B: 1024 chunks
            int c = tid + q * 256;
            int row = c >> 2, seg = c & 3;
            CP_ASYNC16(base + A_TILE_B + row * ROW_B + seg * 16,
                       Bg + (size_t)row * 1024 + k0 + seg * 8);
        }
    };

    int lrow = lane & 15, lkseg = (lane >> 4) * 8;

    stage_load(0, 0); CP_COMMIT();
    stage_load(1, 1); CP_COMMIT();
    stage_load(2, 2); CP_COMMIT();

    const int NKT = 1024 / KC;   // 32
    for (int kt = 0; kt < NKT; kt++) {
        if (kt + 3 < NKT) stage_load(kt + 3, (kt + 3) & 3);
        CP_COMMIT();
        CP_WAIT3();
        __syncthreads();

        uint32_t base = sbase + (kt & 3) * STAGE_B;
        uint32_t aS = base, bS = base + A_TILE_B;

#pragma unroll
        for (int ks = 0; ks < KC / 16; ks++) {
            int kb = (ks * 16 + lkseg) * 2;
            uint32_t a[4][4], b[4][4];
#pragma unroll
            for (int mt = 0; mt < 4; mt++) {
                uint32_t off = (wm + mt * 16 + lrow) * ROW_B + kb;
                LDSM_X4(a[mt][0], a[mt][1], a[mt][2], a[mt][3], aS + off);
            }
#pragma unroll
            for (int nt = 0; nt < 4; nt++) {
                uint32_t off = (wn + nt * 16 + lrow) * ROW_B + kb;
                LDSM_X4(b[nt][0], b[nt][1], b[nt][2], b[nt][3], bS + off);
            }
#pragma unroll
            for (int mt = 0; mt < 4; mt++) {
#pragma unroll
                for (int j = 0; j < 8; j++) {
                    int nt = j >> 1, hi = j & 1;
                    MMA16816F16(acc[mt][j], a[mt][0], a[mt][1], a[mt][2], a[mt][3],
                                b[nt][hi], b[nt][hi + 2]);
                }
            }
        }
        __syncthreads();
    }

    // ---- epilogue ----
#pragma unroll
    for (int mt = 0; mt < 4; mt++) {
        int m0 = bm + wm + mt * 16 + (lane >> 2);
        int m1 = m0 + 8;
        float rs0 = rowsum[((m0 & 7) << 8) | (m0 >> 7)];   // b=m&7, tbucket=m>>7
        float rs1 = rowsum[((m1 & 7) << 8) | (m1 >> 7)];
#pragma unroll
        for (int j = 0; j < 8; j++) {
            int n = bn + wn + j * 8 + (lane & 3) * 2;
            float b0 = bo[n], b1 = bo[n + 1], v0 = bvo[n], v1 = bvo[n + 1];
            *(float2*)(out + (size_t)m0 * 1024 + n) =
                make_float2(acc[mt][j][0] + b0 + rs0 * v0, acc[mt][j][1] + b1 + rs0 * v1);
            *(float2*)(out + (size_t)m1 * 1024 + n) =
                make_float2(acc[mt][j][2] + b0 + rs1 * v0, acc[mt][j][3] + b1 + rs1 * v1);
        }
    }
}

// =================== elementwise / small kernels ===================
__global__ void bucket_mean_kernel(const float* __restrict__ X, float* __restrict__ out) {
    int o = blockIdx.x * 256 + threadIdx.x;
    int e = o & (E_DIM - 1);
    int m = o >> 10;
    int b = m >> 8;
    int i = m & 255;
    const float* src = X + (size_t)(i * BUCKET) * (B_DIM * E_DIM) + b * E_DIM + e;
    float s = 0.f;
#pragma unroll
    for (int pos = 0; pos < BUCKET; pos++) s += src[(size_t)pos * (B_DIM * E_DIM)];
    out[o] = s * (1.0f / BUCKET);
}

__global__ void kpmb_kernel(const unsigned char* __restrict__ mask, int* __restrict__ kpmb) {
    int j = blockIdx.x * 256 + threadIdx.x;
    if (j >= B_DIM * NB) return;
    int b = j >> 8, s = j & 255;
    const unsigned char* m = mask + b * S_DIM + s * BUCKET;
    int all = 1;
#pragma unroll
    for (int t = 0; t < BUCKET; t++) all &= (m[t] != 0);
    kpmb[j] = all;
}

__global__ void mask_kernel(float* __restrict__ la, const int* __restrict__ kpmb) {
    int idx = blockIdx.x * 256 + threadIdx.x;
    int b = idx >> 16, i = (idx >> 8) & 255, j = idx & 255;
    if (kpmb[b * 256 + i] != kpmb[b * 256 + j]) la[idx] = -1e30f;
}

__global__ void bvo_kernel(const float* __restrict__ Wo, const float* __restrict__ bv,
                           float* __restrict__ bvo) {
    int g = blockIdx.x * 8 + (threadIdx.x >> 5);
    int l = threadIdx.x & 31;
    if (g >= E_DIM) return;
    float s = 0.f;
    for (int k = l; k < E_DIM; k += 32) s += Wo[(size_t)g * E_DIM + k] * bv[k];
#pragma unroll
    for (int off = 16; off; off >>= 1) s += __shfl_xor_sync(0xffffffffu, s, off);
    if (l == 0) bvo[g] = s;
}

__global__ void cvt_h_kernel(const float* __restrict__ X, __half* __restrict__ H, int n) {
    int i = blockIdx.x * 256 + threadIdx.x;
    if (i < n) H[i] = __float2half_rn(X[i]);
}

// ---------------- generic fp32 tiled GEMM (projections / attn / wvo) ----------------
template <bool BTRANS, bool BIAS>
__global__ __launch_bounds__(256, 2)
void gemm128_kernel(float* __restrict__ C, const float* __restrict__ A, const float* __restrict__ B,
                    const float* __restrict__ bias,
                    int M, int N, int K, float alpha,
                    long sA, long sB, long sC) {
    __shared__ float As[8][132];
    __shared__ float Bs[8][132];
    int z = blockIdx.z;
    A += (long)z * sA; B += (long)z * sB; C += (long)z * sC;
    int bm = blockIdx.y * 128, bn = blockIdx.x * 128;
    int tid = threadIdx.x, tx = tid & 15, ty = tid >> 4;
    float acc[8][8];
#pragma unroll
    for (int i = 0; i < 8; i++)
#pragma unroll
        for (int j = 0; j < 8; j++) acc[i][j] = 0.f;

    for (int k0 = 0; k0 < K; k0 += 8) {
        {
            int row = tid >> 1, part = tid & 1;
            float4 a4 = *(const float4*)(A + (size_t)(bm + row) * K + k0 + part * 4);
            As[part * 4 + 0][row] = a4.x; As[part * 4 + 1][row] = a4.y;
            As[part * 4 + 2][row] = a4.z; As[part * 4 + 3][row] = a4.w;
        }
        if (!BTRANS) {
            int row = tid >> 1, part = tid & 1;
            float4 b4 = *(const float4*)(B + (size_t)(bn + row) * K + k0 + part * 4);
            Bs[part * 4 + 0][row] = b4.x; Bs[part * 4 + 1][row] = b4.y;
            Bs[part * 4 + 2][row] = b4.z; Bs[part * 4 + 3][row] = b4.w;
        } else {
            int kk = tid >> 5, n4 = (tid & 31) * 4;
            *(float4*)&Bs[kk][n4] = *(const float4*)(B + (size_t)(k0 + kk) * N + bn + n4);
        }
        __syncthreads();
#pragma unroll
        for (int k = 0; k < 8; k++) {
            float4 a0 = *(float4*)&As[k][ty * 8];
            float4 a1 = *(float4*)&As[k][ty * 8 + 4];
            float4 b0 = *(float4*)&Bs[k][tx * 8];
            float4 b1 = *(float4*)&Bs[k][tx * 8 + 4];
            float ra[8] = {a0.x, a0.y, a0.z, a0.w, a1.x, a1.y, a1.z, a1.w};
            float rb[8] = {b0.x, b0.y, b0.z, b0.w, b1.x, b1.y, b1.z, b1.w};
#pragma unroll
            for (int i = 0; i < 8; i++)
#pragma unroll
                for (int j = 0; j < 8; j++) acc[i][j] = fmaf(ra[i], rb[j], acc[i][j]);
        }
        __syncthreads();
    }

#pragma unroll
    for (int i = 0; i < 8; i++) {
        int m = bm + ty * 8 + i;
        float o[8];
#pragma unroll
        for (int j = 0; j < 8; j++) {
            int n = bn + tx * 8 + j;
            float v = acc[i][j] * alpha;
            if (BIAS) v += bias[n];
            o[j] = v;
        }
        float4* dst = (float4*)(C + (size_t)m * N + bn + tx * 8);
        dst[0] = make_float4(o[0], o[1], o[2], o[3]);
        dst[1] = make_float4(o[4], o[5], o[6], o[7]);
    }
}

// ---------------- fused sinkhorn ----------------
__global__ __launch_bounds__(1024, 1)
void sinkhorn_kernel(float* __restrict__ la, float* __restrict__ p, float* __restrict__ rowsum) {
    int b = blockIdx.x;
    float* base = la + b * (NB * NB);
    int tid = threadIdx.x, w = tid >> 5, l = tid & 31;
    __shared__ float sh[32 * 256];
    __shared__ float colv[256];

    for (int it = 0; it < 8; it++) {
#pragma unroll
        for (int ri = 0; ri < 8; ri++) {
            int r = w * 8 + ri;
            float v[8];
#pragma unroll
            for (int ci = 0; ci < 8; ci++) v[ci] = base[r * 256 + ci * 32 + l];
            float m = v[0];
#pragma unroll
            for (int ci = 1; ci < 8; ci++) m = fmaxf(m, v[ci]);
#pragma unroll
            for (int off = 16; off; off >>= 1) m = fmaxf(m, __shfl_xor_sync(0xffffffffu, m, off));
            float s = 0.f;
#pragma unroll
            for (int ci = 0; ci < 8; ci++) s += __expf(v[ci] - m);
#pragma unroll
            for (int off = 16; off; off >>= 1) s += __shfl_xor_sync(0xffffffffu, s, off);
            float lse = m + __logf(s);
#pragma unroll
            for (int ci = 0; ci < 8; ci++) base[r * 256 + ci * 32 + l] = v[ci] - lse;
        }
        __syncthreads();
        float pm[8];
#pragma unroll
        for (int ci = 0; ci < 8; ci++) pm[ci] = -3.4e38f;
#pragma unroll
        for (int ri = 0; ri < 8; ri++)
#pragma unroll
            for (int ci = 0; ci < 8; ci++)
                pm[ci] = fmaxf(pm[ci], base[(w * 8 + ri) * 256 + ci * 32 + l]);
#pragma unroll
        for (int ci = 0; ci < 8; ci++) sh[w * 256 + ci * 32 + l] = pm[ci];
        __syncthreads();
        if (tid < 256) {
            float m = sh[tid];
#pragma unroll 4
            for (int ww = 1; ww < 32; ww++) m = fmaxf(m, sh[ww * 256 + tid]);
            colv[tid] = m;
        }
        __syncthreads();
        float ps[8];
#pragma unroll
        for (int ci = 0; ci < 8; ci++) ps[ci] = 0.f;
#pragma unroll
        for (int ri = 0; ri < 8; ri++)
#pragma unroll
            for (int ci = 0; ci < 8; ci++)
                ps[ci] += __expf(base[(w * 8 + ri) * 256 + ci * 32 + l] - colv[ci * 32 + l]);
#pragma unroll
        for (int ci = 0; ci < 8; ci++) sh[w * 256 + ci * 32 + l] = ps[ci];
        __syncthreads();
        if (tid < 256) {
            float s = 0.f;
#pragma unroll 4
            for (int ww = 0; ww < 32; ww++) s += sh[ww * 256 + tid];
            colv[tid] += __logf(s);
        }
        __syncthreads();
#pragma unroll
        for (int ri = 0; ri < 8; ri++)
#pragma unroll
            for (int ci = 0; ci < 8; ci++)
                base[(w * 8 + ri) * 256 + ci * 32 + l] -= colv[ci * 32 + l];
        __syncthreads();
    }

#pragma unroll
    for (int ri = 0; ri < 8; ri++) {
        int r = w * 8 + ri;
        float s = 0.f;
#pragma unroll
        for (int ci = 0; ci < 8; ci++) {
            float e = __expf(base[r * 256 + ci * 32 + l]);
            p[b * (NB * NB) + r * 256 + ci * 32 + l] = e;
            s += e;
        }
#pragma unroll
        for (int off = 16; off; off >>= 1) s += __shfl_xor_sync(0xffffffffu, s, off);
        if (l == 0) rowsum[b * 256 + r] = s;
    }
}

// ---------------- bucket mix on RAW value -> fp16 Z ----------------
__global__ __launch_bounds__(256, 2)
void zmix_kernel(const float* __restrict__ value, const float* __restrict__ p,
                 __half* __restrict__ Zh) {
    int et = blockIdx.x, pos = blockIdx.y, b = blockIdx.z;
    __shared__ float sp[16][256];
    __shared__ float sv[16][68];
    int tid = threadIdx.x, tx = tid & 15, ty = tid >> 4;
    float acc[16][4];
#pragma unroll
    for (int k = 0; k < 16; k++)
#pragma unroll
        for (int j = 0; j < 4; j++) acc[k][j] = 0.f;

    const float* pb = p + b * (NB * NB);
    for (int s0 = 0; s0 < 256; s0 += 16) {
        {
            const float4* src = (const float4*)(pb + (size_t)tid * 256 + s0);
#pragma unroll
            for (int q = 0; q < 4; q++) {
                float4 v = src[q];
                sp[q * 4 + 0][tid] = v.x; sp[q * 4 + 1][tid] = v.y;
                sp[q * 4 + 2][tid] = v.z; sp[q * 4 + 3][tid] = v.w;
            }
        }
        {
            int si = tid >> 4, j = tid & 15;
            float4 v = *(const float4*)(value +
                (size_t)((s0 + si) * BUCKET + pos) * (B_DIM * E_DIM) + b * E_DIM + et * 64 + j * 4);
            *(float4*)&sv[si][j * 4] = v;
        }
        __syncthreads();
#pragma unroll
        for (int si = 0; si < 16; si++) {
            float4 rv = *(float4*)&sv[si][tx * 4];
#pragma unroll
            for (int k = 0; k < 16; k++) {
                float a = sp[si][ty + (k << 4)];
                acc[k][0] = fmaf(a, rv.x, acc[k][0]);
                acc[k][1] = fmaf(a, rv.y, acc[k][1]);
                acc[k][2] = fmaf(a, rv.z, acc[k][2]);
                acc[k][3] = fmaf(a, rv.w, acc[k][3]);
            }
        }
        __syncthreads();
    }
#pragma unroll
    for (int k = 0; k < 16; k++) {
        int tb = k * 16 + ty;
        size_t off = (size_t)((tb * BUCKET + pos) * B_DIM + b) * E_DIM + et * 64 + tx * 4;
        __half h[4];
#pragma unroll
        for (int j = 0; j < 4; j++) h[j] = __float2half_rn(acc[k][j]);
        *(uint2*)(Zh + off) = *(uint2*)h;
    }
}

// ---------------- launch ----------------
extern "C" void kernel_launch(void* const* d_in, const int* in_sizes, int n_in,
                              void* d_out, int out_size) {
    const float* query = (const float*)d_in[0];
    const float* key_t = (const float*)d_in[1];
    const float* value = (const float*)d_in[2];
    const unsigned char* kpm = (const unsigned char*)d_in[3];
    const float* Wq = (const float*)d_in[4];
    const float* bq = (const float*)d_in[5];
    const float* Wk = (const float*)d_in[6];
    const float* bk = (const float*)d_in[7];
    const float* Wv = (const float*)d_in[8];
    const float* bv = (const float*)d_in[9];
    const float* Wo = (const float*)d_in[10];
    const float* bo = (const float*)d_in[11];
    float* out = (float*)d_out;

    float *qm, *km, *qb, *kb, *la, *p, *rowsum, *wvo, *bvo;
    __half *zh, *wvoh;
    int* kpmb;
    cudaGetSymbolAddress((void**)&qm, g_qm);
    cudaGetSymbolAddress((void**)&km, g_km);
    cudaGetSymbolAddress((void**)&qb, g_qb);
    cudaGetSymbolAddress((void**)&kb, g_kb);
    cudaGetSymbolAddress((void**)&la, g_la);
    cudaGetSymbolAddress((void**)&p, g_p);
    cudaGetSymbolAddress((void**)&rowsum, g_rowsum);
    cudaGetSymbolAddress((void**)&kpmb, g_kpmb);
    cudaGetSymbolAddress((void**)&wvo, g_wvo);
    cudaGetSymbolAddress((void**)&bvo, g_bvo);
    cudaGetSymbolAddress((void**)&zh, g_zh);
    cudaGetSymbolAddress((void**)&wvoh, g_wvoh);

    static bool attr_set = false;
    if (!attr_set) {
        cudaFuncSetAttribute(hmma_out_kernel, cudaFuncAttributeMaxDynamicSharedMemorySize, HMMA_SMEM);
        attr_set = true;
    }

    // 1) bucket means of raw query/key
    bucket_mean_kernel<<<(B_DIM * NB * E_DIM) / 256, 256>>>(query, qm);
    bucket_mean_kernel<<<(B_DIM * NB * E_DIM) / 256, 256>>>(key_t, km);

    // 2) project bucket means
    gemm128_kernel<false, true><<<dim3(8, 16, 1), 256>>>(
        qb, qm, Wq, bq, 2048, 1024, 1024, 1.0f, 0, 0, 0);
    gemm128_kernel<false, true><<<dim3(8, 16, 1), 256>>>(
        kb, km, Wk, bk, 2048, 1024, 1024, 1.0f, 0, 0, 0);

    // 3) fold Wv into Wo, convert to fp16; bvo = Wo @ bv
    gemm128_kernel<true, false><<<dim3(8, 8, 1), 256>>>(
        wvo, Wo, Wv, nullptr, 1024, 1024, 1024, 1.0f, 0, 0, 0);
    cvt_h_kernel<<<(E_DIM * E_DIM) / 256, 256>>>(wvo, wvoh, E_DIM * E_DIM);
    bvo_kernel<<<128, 256>>>(Wo, bv, bvo);

    // 4) attn logits
    gemm128_kernel<false, false><<<dim3(2, 2, B_DIM), 256>>>(
        la, qb, kb, nullptr, 256, 256, 1024, ATTN_ALPHA,
        (long)NB * E_DIM, (long)NB * E_DIM, (long)NB * NB);

    // 5) mask
    kpmb_kernel<<<8, 256>>>(kpm, kpmb);
    mask_kernel<<<(B_DIM * NB * NB) / 256, 256>>>(la, kpmb);

    // 6) sinkhorn
    sinkhorn_kernel<<<B_DIM, 1024>>>(la, p, rowsum);

    // 7) bucket mix -> fp16 Z
    zmix_kernel<<<dim3(16, 16, B_DIM), 256>>>(value, p, zh);

    // 8) final: fp16 warp-MMA GEMM (M=32768, N=1024, K=1024)
    hmma_out_kernel<<<dim3(4, 256, 1), 256, HMMA_SMEM>>>(
        out, zh, wvoh, bo, bvo, rowsum);
}

// round 6
// speedup vs baseline: 2.4836x; 1.3622x over previous
#include <cuda_runtime.h>
#include <cuda_bf16.h>
#include <cuda_fp16.h>
#include <math.h>
#include <cstdint>

// ---------------- problem constants ----------------
#define T_DIM 4096
#define S_DIM 4096
#define B_DIM 8
#define E_DIM 1024
#define BUCKET 16
#define NB 256            // T/BUCKET
#define TAU 0.75f
#define ATTN_ALPHA (1.0f/(32.0f*0.75f))

// ---------------- scratch (device globals; no allocation allowed) ----------------
__device__ float g_qm[B_DIM*NB*E_DIM];
__device__ float g_km[B_DIM*NB*E_DIM];
__device__ float g_qb[B_DIM*NB*E_DIM];
__device__ float g_kb[B_DIM*NB*E_DIM];
__device__ float g_la[B_DIM*NB*NB];
__device__ __half g_ph[B_DIM*NB*NB];        // sinkhorn result, fp16
__device__ float g_rowsum[B_DIM*NB];
__device__ int   g_kpmb[B_DIM*NB];
__device__ float g_wvo[E_DIM*E_DIM];        // Wo @ Wv  (row-major E x E)
__device__ float g_bvo[E_DIM];              // Wo @ bv
__device__ __half g_vh[S_DIM*B_DIM*E_DIM];  // value in fp16, same (S,B,E) layout
__device__ __half g_zh[T_DIM*B_DIM*E_DIM];  // mixed value, fp16 (rows m=t*8+b, 1024 cols)
__device__ __half g_wvoh[E_DIM*E_DIM];      // wvo in fp16

// =================== warp-MMA helpers (compute_80-compatible PTX) ===================
__device__ __forceinline__ uint32_t smem_u32(const void* p) {
    uint32_t a;
    asm("{ .reg .u64 t; cvta.to.shared.u64 t, %1; cvt.u32.u64 %0, t; }" : "=r"(a) : "l"(p));
    return a;
}

#define CP_ASYNC16(dst, src) \
    asm volatile("cp.async.cg.shared.global [%0], [%1], 16;" :: "r"(dst), "l"(src))
#define CP_COMMIT() asm volatile("cp.async.commit_group;")
#define CP_WAIT3()  asm volatile("cp.async.wait_group 3;")
#define CP_WAIT1()  asm volatile("cp.async.wait_group 1;")
#define CP_WAIT0()  asm volatile("cp.async.wait_group 0;")

#define LDSM_X4(r0, r1, r2, r3, addr) \
    asm volatile("ldmatrix.sync.aligned.m8n8.x4.shared.b16 {%0,%1,%2,%3}, [%4];" \
        : "=r"(r0), "=r"(r1), "=r"(r2), "=r"(r3) : "r"(addr))

#define LDSM_X4_T(r0, r1, r2, r3, addr) \
    asm volatile("ldmatrix.sync.aligned.m8n8.x4.trans.shared.b16 {%0,%1,%2,%3}, [%4];" \
        : "=r"(r0), "=r"(r1), "=r"(r2), "=r"(r3) : "r"(addr))

#define MMA16816F16(d, a0, a1, a2, a3, b0, b1) \
    asm volatile("mma.sync.aligned.m16n8k16.row.col.f32.f16.f16.f32 " \
        "{%0,%1,%2,%3}, {%4,%5,%6,%7}, {%8,%9}, {%0,%1,%2,%3};" \
        : "+f"((d)[0]), "+f"((d)[1]), "+f"((d)[2]), "+f"((d)[3]) \
        : "r"(a0), "r"(a1), "r"(a2), "r"(a3), "r"(b0), "r"(b1))

// =================== final GEMM: out = Zh*Wh' + bo + rowsum*bvo ===================
// CTA tile 128(M) x 256(N), warps 2x4 (warp tile 64x64), KC=32, 4-stage cp.async.
#define KC 32
#define ROW_B 80                      // fp16 row stride in bytes (32*2 + 16 pad)
#define A_TILE_B (128*ROW_B)          // 10240
#define B_TILE_B (256*ROW_B)          // 20480
#define STAGE_B (A_TILE_B + B_TILE_B) // 30720
#define HMMA_SMEM (4*STAGE_B)         // 122880

__global__ __launch_bounds__(256, 1)
void hmma_out_kernel(float* __restrict__ out,
                     const __half* __restrict__ Ah, const __half* __restrict__ Bh,
                     const float* __restrict__ bo, const float* __restrict__ bvo,
                     const float* __restrict__ rowsum) {
    extern __shared__ char smem[];
    uint32_t sbase = smem_u32(smem);

    int tid = threadIdx.x, wid = tid >> 5, lane = tid & 31;
    int bm = blockIdx.y * 128, bn = blockIdx.x * 256;
    int wm = (wid & 1) * 64, wn = (wid >> 1) * 64;

    const __half* Ag = Ah + (size_t)bm * 1024;
    const __half* Bg = Bh + (size_t)bn * 1024;

    float acc[4][8][4];
#pragma unroll
    for (int i = 0; i < 4; i++)
#pragma unroll
        for (int j = 0; j < 8; j++)
#pragma unroll
            for (int r = 0; r < 4; r++) acc[i][j][r] = 0.f;

    auto stage_load = [&](int kt, int buf) {
        int k0 = kt * KC;
        uint32_t base = sbase + buf * STAGE_B;
#pragma unroll
        for (int q = 0; q < 2; q++) {
            int c = tid + q * 256;
            int row = c >> 2, seg = c & 3;
            CP_ASYNC16(base + row * ROW_B + seg * 16,
                       Ag + (size_t)row * 1024 + k0 + seg * 8);
        }
#pragma unroll
        for (int q = 0; q < 4; q++) {
            int c = tid + q * 256;
            int row = c >> 2, seg = c & 3;
            CP_ASYNC16(base + A_TILE_B + row * ROW_B + seg * 16,
                       Bg + (size_t)row * 1024 + k0 + seg * 8);
        }
    };

    int lrow = lane & 15, lkseg = (lane >> 4) * 8;

    stage_load(0, 0); CP_COMMIT();
    stage_load(1, 1); CP_COMMIT();
    stage_load(2, 2); CP_COMMIT();

    const int NKT = 1024 / KC;   // 32
    for (int kt = 0; kt < NKT; kt++) {
        if (kt + 3 < NKT) stage_load(kt + 3, (kt + 3) & 3);
        CP_COMMIT();
        CP_WAIT3();
        __syncthreads();

        uint32_t base = sbase + (kt & 3) * STAGE_B;
        uint32_t aS = base, bS = base + A_TILE_B;

#pragma unroll
        for (int ks = 0; ks < KC / 16; ks++) {
            int kb = (ks * 16 + lkseg) * 2;
            uint32_t a[4][4], b[4][4];
#pragma unroll
            for (int mt = 0; mt < 4; mt++) {
                uint32_t off = (wm + mt * 16 + lrow) * ROW_B + kb;
                LDSM_X4(a[mt][0], a[mt][1], a[mt][2], a[mt][3], aS + off);
            }
#pragma unroll
            for (int nt = 0; nt < 4; nt++) {
                uint32_t off = (wn + nt * 16 + lrow) * ROW_B + kb;
                LDSM_X4(b[nt][0], b[nt][1], b[nt][2], b[nt][3], bS + off);
            }
#pragma unroll
            for (int mt = 0; mt < 4; mt++) {
#pragma unroll
                for (int j = 0; j < 8; j++) {
                    int nt = j >> 1, hi = j & 1;
                    MMA16816F16(acc[mt][j], a[mt][0], a[mt][1], a[mt][2], a[mt][3],
                                b[nt][hi], b[nt][hi + 2]);
                }
            }
        }
        __syncthreads();
    }

#pragma unroll
    for (int mt = 0; mt < 4; mt++) {
        int m0 = bm + wm + mt * 16 + (lane >> 2);
        int m1 = m0 + 8;
        float rs0 = rowsum[((m0 & 7) << 8) | (m0 >> 7)];
        float rs1 = rowsum[((m1 & 7) << 8) | (m1 >> 7)];
#pragma unroll
        for (int j = 0; j < 8; j++) {
            int n = bn + wn + j * 8 + (lane & 3) * 2;
            float b0 = bo[n], b1 = bo[n + 1], v0 = bvo[n], v1 = bvo[n + 1];
            *(float2*)(out + (size_t)m0 * 1024 + n) =
                make_float2(acc[mt][j][0] + b0 + rs0 * v0, acc[mt][j][1] + b1 + rs0 * v1);
            *(float2*)(out + (size_t)m1 * 1024 + n) =
                make_float2(acc[mt][j][2] + b0 + rs1 * v0, acc[mt][j][3] + b1 + rs1 * v1);
        }
    }
}

// =================== zmix as fp16 warp-MMA: Z_pos[tb,e] = sum_s P[tb,s]*Vh[16s+pos][b][e] ===
// CTA 128(M=tb) x 128(N=e), K=256, KC=32, double buffer. grid (8 etile, 2 mtile*16 pos, 8 b)
#define ZA_ROW_B 80
#define ZA_TILE_B (128*ZA_ROW_B)       // 10240
#define ZB_ROW_B 272                   // 128 fp16 + 16B pad
#define ZB_TILE_B (32*ZB_ROW_B)        // 8704
#define ZSTAGE_B (ZA_TILE_B + ZB_TILE_B)
#define ZSMEM (2*ZSTAGE_B)             // 37888 (< 48K, no attribute needed)

__global__ __launch_bounds__(256, 1)
void zmix_hmma_kernel(const __half* __restrict__ Ph, const __half* __restrict__ Vh,
                      __half* __restrict__ Zh) {
    extern __shared__ char smem[];
    uint32_t sbase = smem_u32(smem);

    int tid = threadIdx.x, wid = tid >> 5, lane = tid & 31;
    int b = blockIdx.z;
    int pos = blockIdx.y >> 1, mt0 = blockIdx.y & 1;
    int bm = mt0 * 128, bn = blockIdx.x * 128;
    int wm = (wid & 1) * 64, wn = (wid >> 1) * 32;

    const __half* Ag = Ph + (size_t)b * (NB * NB) + (size_t)bm * 256;

    float acc[4][4][4];
#pragma unroll
    for (int i = 0; i < 4; i++)
#pragma unroll
        for (int j = 0; j < 4; j++)
#pragma unroll
            for (int r = 0; r < 4; r++) acc[i][j][r] = 0.f;

    auto stage_load = [&](int kt, int buf) {
        int k0 = kt * 32;
        uint32_t base = sbase + buf * ZSTAGE_B;
        // A: P tile 128 x 32 (4 chunks/row)
#pragma unroll
        for (int q = 0; q < 2; q++) {
            int c = tid + q * 256;
            int row = c >> 2, seg = c & 3;
            CP_ASYNC16(base + row * ZA_ROW_B + seg * 16,
                       Ag + (size_t)row * 256 + k0 + seg * 8);
        }
        // B: Vh rows 16*(k0+kk)+pos, cols bn..bn+127 (16 chunks/row)
#pragma unroll
        for (int q = 0; q < 2; q++) {
            int c = tid + q * 256;
            int kk = c >> 4, seg = c & 15;
            size_t grow = (size_t)(16 * (k0 + kk) + pos) * (B_DIM * E_DIM) + b * E_DIM + bn;
            CP_ASYNC16(base + ZA_TILE_B + kk * ZB_ROW_B + seg * 16, Vh + grow + seg * 8);
        }
        CP_COMMIT();
    };

    int lrow = lane & 15, lhi = lane >> 4;

    stage_load(0, 0);
    for (int kt = 0; kt < 8; kt++) {
        if (kt + 1 < 8) { stage_load(kt + 1, (kt + 1) & 1); CP_WAIT1(); }
        else CP_WAIT0();
        __syncthreads();

        uint32_t base = sbase + (kt & 1) * ZSTAGE_B;
        uint32_t aS = base, bS = base + ZA_TILE_B;

#pragma unroll
        for (int ks = 0; ks < 2; ks++) {
            uint32_t a[4][4], bt[2][4];
#pragma unroll
            for (int mt = 0; mt < 4; mt++) {
                uint32_t off = (wm + mt * 16 + lrow) * ZA_ROW_B + (ks * 16 + lhi * 8) * 2;
                LDSM_X4(a[mt][0], a[mt][1], a[mt][2], a[mt][3], aS + off);
            }
#pragma unroll
            for (int ng = 0; ng < 2; ng++) {
                uint32_t off = (ks * 16 + lrow) * ZB_ROW_B + (wn + ng * 16 + lhi * 8) * 2;
                LDSM_X4_T(bt[ng][0], bt[ng][1], bt[ng][2], bt[ng][3], bS + off);
            }
#pragma unroll
            for (int mt = 0; mt < 4; mt++) {
#pragma unroll
                for (int j = 0; j < 4; j++) {
                    int ng = j >> 1, hi = j & 1;
                    MMA16816F16(acc[mt][j], a[mt][0], a[mt][1], a[mt][2], a[mt][3],
                                bt[ng][hi * 2], bt[ng][hi * 2 + 1]);
                }
            }
        }
        __syncthreads();
    }

    // epilogue: Zh[((tb*16+pos)*8 + b)*1024 + e]
#pragma unroll
    for (int mt = 0; mt < 4; mt++) {
        int tb0 = bm + wm + mt * 16 + (lane >> 2);
        int tb1 = tb0 + 8;
        size_t r0 = ((size_t)(tb0 * 16 + pos) * 8 + b) * 1024;
        size_t r1 = ((size_t)(tb1 * 16 + pos) * 8 + b) * 1024;
#pragma unroll
        for (int j = 0; j < 4; j++) {
            int e = bn + wn + j * 8 + (lane & 3) * 2;
            *(__half2*)(Zh + r0 + e) = __floats2half2_rn(acc[mt][j][0], acc[mt][j][1]);
            *(__half2*)(Zh + r1 + e) = __floats2half2_rn(acc[mt][j][2], acc[mt][j][3]);
        }
    }
}

// =================== elementwise / small kernels ===================
__global__ void bucket_mean_kernel(const float* __restrict__ X, float* __restrict__ out) {
    int o = blockIdx.x * 256 + threadIdx.x;
    int e = o & (E_DIM - 1);
    int m = o >> 10;
    int b = m >> 8;
    int i = m & 255;
    const float* src = X + (size_t)(i * BUCKET) * (B_DIM * E_DIM) + b * E_DIM + e;
    float s = 0.f;
#pragma unroll
    for (int pos = 0; pos < BUCKET; pos++) s += src[(size_t)pos * (B_DIM * E_DIM)];
    out[o] = s * (1.0f / BUCKET);
}

__global__ void kpmb_kernel(const unsigned char* __restrict__ mask, int* __restrict__ kpmb) {
    int j = blockIdx.x * 256 + threadIdx.x;
    if (j >= B_DIM * NB) return;
    int b = j >> 8, s = j & 255;
    const unsigned char* m = mask + b * S_DIM + s * BUCKET;
    int all = 1;
#pragma unroll
    for (int t = 0; t < BUCKET; t++) all &= (m[t] != 0);
    kpmb[j] = all;
}

__global__ void mask_kernel(float* __restrict__ la, const int* __restrict__ kpmb) {
    int idx = blockIdx.x * 256 + threadIdx.x;
    int b = idx >> 16, i = (idx >> 8) & 255, j = idx & 255;
    if (kpmb[b * 256 + i] != kpmb[b * 256 + j]) la[idx] = -1e30f;
}

__global__ void bvo_kernel(const float* __restrict__ Wo, const float* __restrict__ bv,
                           float* __restrict__ bvo) {
    int g = blockIdx.x * 8 + (threadIdx.x >> 5);
    int l = threadIdx.x & 31;
    if (g >= E_DIM) return;
    float s = 0.f;
    for (int k = l; k < E_DIM; k += 32) s += Wo[(size_t)g * E_DIM + k] * bv[k];
#pragma unroll
    for (int off = 16; off; off >>= 1) s += __shfl_xor_sync(0xffffffffu, s, off);
    if (l == 0) bvo[g] = s;
}

__global__ void cvt_h_kernel(const float* __restrict__ X, __half* __restrict__ H, int n) {
    int i = blockIdx.x * 256 + threadIdx.x;
    if (i < n) H[i] = __float2half_rn(X[i]);
}

// vectorized fp32 -> fp16 (8 elements / thread)
__global__ void cvt_value_kernel(const float* __restrict__ X, __half* __restrict__ H) {
    size_t i = ((size_t)blockIdx.x * 256 + threadIdx.x) * 8;
    float4 a = *(const float4*)(X + i);
    float4 c = *(const float4*)(X + i + 4);
    __half2 h[4];
    h[0] = __floats2half2_rn(a.x, a.y);
    h[1] = __floats2half2_rn(a.z, a.w);
    h[2] = __floats2half2_rn(c.x, c.y);
    h[3] = __floats2half2_rn(c.z, c.w);
    *(uint4*)(H + i) = *(uint4*)h;
}

// ---------------- generic fp32 tiled GEMM (projections / attn / wvo) ----------------
template <bool BTRANS, bool BIAS>
__global__ __launch_bounds__(256, 2)
void gemm128_kernel(float* __restrict__ C, const float* __restrict__ A, const float* __restrict__ B,
                    const float* __restrict__ bias,
                    int M, int N, int K, float alpha,
                    long sA, long sB, long sC) {
    __shared__ float As[8][132];
    __shared__ float Bs[8][132];
    int z = blockIdx.z;
    A += (long)z * sA; B += (long)z * sB; C += (long)z * sC;
    int bm = blockIdx.y * 128, bn = blockIdx.x * 128;
    int tid = threadIdx.x, tx = tid & 15, ty = tid >> 4;
    float acc[8][8];
#pragma unroll
    for (int i = 0; i < 8; i++)
#pragma unroll
        for (int j = 0; j < 8; j++) acc[i][j] = 0.f;

    for (int k0 = 0; k0 < K; k0 += 8) {
        {
            int row = tid >> 1, part = tid & 1;
            float4 a4 = *(const float4*)(A + (size_t)(bm + row) * K + k0 + part * 4);
            As[part * 4 + 0][row] = a4.x; As[part * 4 + 1][row] = a4.y;
            As[part * 4 + 2][row] = a4.z; As[part * 4 + 3][row] = a4.w;
        }
        if (!BTRANS) {
            int row = tid >> 1, part = tid & 1;
            float4 b4 = *(const float4*)(B + (size_t)(bn + row) * K + k0 + part * 4);
            Bs[part * 4 + 0][row] = b4.x; Bs[part * 4 + 1][row] = b4.y;
            Bs[part * 4 + 2][row] = b4.z; Bs[part * 4 + 3][row] = b4.w;
        } else {
            int kk = tid >> 5, n4 = (tid & 31) * 4;
            *(float4*)&Bs[kk][n4] = *(const float4*)(B + (size_t)(k0 + kk) * N + bn + n4);
        }
        __syncthreads();
#pragma unroll
        for (int k = 0; k < 8; k++) {
            float4 a0 = *(float4*)&As[k][ty * 8];
            float4 a1 = *(float4*)&As[k][ty * 8 + 4];
            float4 b0 = *(float4*)&Bs[k][tx * 8];
            float4 b1 = *(float4*)&Bs[k][tx * 8 + 4];
            float ra[8] = {a0.x, a0.y, a0.z, a0.w, a1.x, a1.y, a1.z, a1.w};
            float rb[8] = {b0.x, b0.y, b0.z, b0.w, b1.x, b1.y, b1.z, b1.w};
#pragma unroll
            for (int i = 0; i < 8; i++)
#pragma unroll
                for (int j = 0; j < 8; j++) acc[i][j] = fmaf(ra[i], rb[j], acc[i][j]);
        }
        __syncthreads();
    }

#pragma unroll
    for (int i = 0; i < 8; i++) {
        int m = bm + ty * 8 + i;
        float o[8];
#pragma unroll
        for (int j = 0; j < 8; j++) {
            int n = bn + tx * 8 + j;
            float v = acc[i][j] * alpha;
            if (BIAS) v += bias[n];
            o[j] = v;
        }
        float4* dst = (float4*)(C + (size_t)m * N + bn + tx * 8);
        dst[0] = make_float4(o[0], o[1], o[2], o[3]);
        dst[1] = make_float4(o[4], o[5], o[6], o[7]);
    }
}

// ---------------- fused sinkhorn: ONE read+write pass per iteration ----------------
// Invariant: colv holds the pending column-LSE correction (applied lazily).
// After row normalization all entries <= 0, so column LSE needs no max.
__global__ __launch_bounds__(1024, 1)
void sinkhorn_kernel(float* __restrict__ la, __half* __restrict__ ph, float* __restrict__ rowsum) {
    int b = blockIdx.x;
    float* base = la + b * (NB * NB);
    int tid = threadIdx.x, w = tid >> 5, l = tid & 31;
    __shared__ float sh[32 * 256];
    __shared__ float colv[256];
    if (tid < 256) colv[tid] = 0.f;
    __syncthreads();

    for (int it = 0; it < 8; it++) {
        float cv[8], cs[8];
#pragma unroll
        for (int ci = 0; ci < 8; ci++) { cv[ci] = colv[ci * 32 + l]; cs[ci] = 0.f; }
#pragma unroll
        for (int ri = 0; ri < 8; ri++) {
            int r = w * 8 + ri;
            float v[8];
#pragma unroll
            for (int ci = 0; ci < 8; ci++) v[ci] = base[r * 256 + ci * 32 + l] - cv[ci];
            float m = v[0];
#pragma unroll
            for (int ci = 1; ci < 8; ci++) m = fmaxf(m, v[ci]);
#pragma unroll
            for (int off = 16; off; off >>= 1) m = fmaxf(m, __shfl_xor_sync(0xffffffffu, m, off));
            float s = 0.f;
#pragma unroll
            for (int ci = 0; ci < 8; ci++) s += __expf(v[ci] - m);
#pragma unroll
            for (int off = 16; off; off >>= 1) s += __shfl_xor_sync(0xffffffffu, s, off);
            float lse = m + __logf(s);
#pragma unroll
            for (int ci = 0; ci < 8; ci++) {
                float wv = v[ci] - lse;
                base[r * 256 + ci * 32 + l] = wv;
                cs[ci] += __expf(wv);
            }
        }
#pragma unroll
        for (int ci = 0; ci < 8; ci++) sh[w * 256 + ci * 32 + l] = cs[ci];
        __syncthreads();
        if (tid < 256) {
            float s = 0.f;
#pragma unroll 4
            for (int ww = 0; ww < 32; ww++) s += sh[ww * 256 + tid];
            colv[tid] = __logf(s);
        }
        __syncthreads();
    }

    // epilogue: p = exp(la - colv) -> fp16 ; rowsum fp32
    float cv[8];
#pragma unroll
    for (int ci = 0; ci < 8; ci++) cv[ci] = colv[ci * 32 + l];
#pragma unroll
    for (int ri = 0; ri < 8; ri++) {
        int r = w * 8 + ri;
        float s = 0.f;
#pragma unroll
        for (int ci = 0; ci < 8; ci++) {
            float e = __expf(base[r * 256 + ci * 32 + l] - cv[ci]);
            ph[b * (NB * NB) + r * 256 + ci * 32 + l] = __float2half_rn(e);
            s += e;
        }
#pragma unroll
        for (int off = 16; off; off >>= 1) s += __shfl_xor_sync(0xffffffffu, s, off);
        if (l == 0) rowsum[b * 256 + r] = s;
    }
}

// ---------------- launch ----------------
extern "C" void kernel_launch(void* const* d_in, const int* in_sizes, int n_in,
                              void* d_out, int out_size) {
    const float* query = (const float*)d_in[0];
    const float* key_t = (const float*)d_in[1];
    const float* value = (const float*)d_in[2];
    const unsigned char* kpm = (const unsigned char*)d_in[3];
    const float* Wq = (const float*)d_in[4];
    const float* bq = (const float*)d_in[5];
    const float* Wk = (const float*)d_in[6];
    const float* bk = (const float*)d_in[7];
    const float* Wv = (const float*)d_in[8];
    const float* bv = (const float*)d_in[9];
    const float* Wo = (const float*)d_in[10];
    const float* bo = (const float*)d_in[11];
    float* out = (float*)d_out;

    float *qm, *km, *qb, *kb, *la, *rowsum, *wvo, *bvo;
    __half *ph, *vh, *zh, *wvoh;
    int* kpmb;
    cudaGetSymbolAddress((void**)&qm, g_qm);
    cudaGetSymbolAddress((void**)&km, g_km);
    cudaGetSymbolAddress((void**)&qb, g_qb);
    cudaGetSymbolAddress((void**)&kb, g_kb);
    cudaGetSymbolAddress((void**)&la, g_la);
    cudaGetSymbolAddress((void**)&ph, g_ph);
    cudaGetSymbolAddress((void**)&rowsum, g_rowsum);
    cudaGetSymbolAddress((void**)&kpmb, g_kpmb);
    cudaGetSymbolAddress((void**)&wvo, g_wvo);
    cudaGetSymbolAddress((void**)&bvo, g_bvo);
    cudaGetSymbolAddress((void**)&vh, g_vh);
    cudaGetSymbolAddress((void**)&zh, g_zh);
    cudaGetSymbolAddress((void**)&wvoh, g_wvoh);

    static bool attr_set = false;
    if (!attr_set) {
        cudaFuncSetAttribute(hmma_out_kernel, cudaFuncAttributeMaxDynamicSharedMemorySize, HMMA_SMEM);
        attr_set = true;
    }

    // 0) value -> fp16
    cvt_value_kernel<<<(S_DIM * B_DIM * E_DIM) / (256 * 8), 256>>>(value, vh);

    // 1) bucket means of raw query/key
    bucket_mean_kernel<<<(B_DIM * NB * E_DIM) / 256, 256>>>(query, qm);
    bucket_mean_kernel<<<(B_DIM * NB * E_DIM) / 256, 256>>>(key_t, km);

    // 2) project bucket means
    gemm128_kernel<false, true><<<dim3(8, 16, 1), 256>>>(
        qb, qm, Wq, bq, 2048, 1024, 1024, 1.0f, 0, 0, 0);
    gemm128_kernel<false, true><<<dim3(8, 16, 1), 256>>>(
        kb, km, Wk, bk, 2048, 1024, 1024, 1.0f, 0, 0, 0);

    // 3) fold Wv into Wo, convert to fp16; bvo = Wo @ bv
    gemm128_kernel<true, false><<<dim3(8, 8, 1), 256>>>(
        wvo, Wo, Wv, nullptr, 1024, 1024, 1024, 1.0f, 0, 0, 0);
    cvt_h_kernel<<<(E_DIM * E_DIM) / 256, 256>>>(wvo, wvoh, E_DIM * E_DIM);
    bvo_kernel<<<128, 256>>>(Wo, bv, bvo);

    // 4) attn logits
    gemm128_kernel<false, false><<<dim3(2, 2, B_DIM), 256>>>(
        la, qb, kb, nullptr, 256, 256, 1024, ATTN_ALPHA,
        (long)NB * E_DIM, (long)NB * E_DIM, (long)NB * NB);

    // 5) mask
    kpmb_kernel<<<8, 256>>>(kpm, kpmb);
    mask_kernel<<<(B_DIM * NB * NB) / 256, 256>>>(la, kpmb);

    // 6) sinkhorn -> ph (fp16), rowsum
    sinkhorn_kernel<<<B_DIM, 1024>>>(la, ph, rowsum);

    // 7) bucket mix via fp16 MMA -> zh
    zmix_hmma_kernel<<<dim3(8, 32, 8), 256, ZSMEM>>>(ph, vh, zh);

    // 8) final: fp16 warp-MMA GEMM (M=32768, N=1024, K=1024)
    hmma_out_kernel<<<dim3(4, 256, 1), 256, HMMA_SMEM>>>(
        out, zh, wvoh, bo, bvo, rowsum);
}

// round 7
// speedup vs baseline: 4.4014x; 1.7722x over previous
#include <cuda_runtime.h>
#include <cuda_bf16.h>
#include <cuda_fp16.h>
#include <math.h>
#include <cstdint>

// ---------------- problem constants ----------------
#define T_DIM 4096
#define S_DIM 4096
#define B_DIM 8
#define E_DIM 1024
#define BUCKET 16
#define NB 256            // T/BUCKET
#define TAU 0.75f
#define ATTN_ALPHA (1.0f/(32.0f*0.75f))

// ---------------- scratch (device globals; no allocation allowed) ----------------
__device__ __half g_qmh[B_DIM*NB*E_DIM];    // bucket means, fp16
__device__ __half g_kmh[B_DIM*NB*E_DIM];
__device__ __half g_qbh[B_DIM*NB*E_DIM];    // projected bucket q/k, fp16
__device__ __half g_kbh[B_DIM*NB*E_DIM];
__device__ __half g_Wqh[E_DIM*E_DIM];
__device__ __half g_Wkh[E_DIM*E_DIM];
__device__ __half g_Wvh[E_DIM*E_DIM];
__device__ __half g_Woh[E_DIM*E_DIM];
__device__ float g_la[B_DIM*NB*NB];
__device__ __half g_ph[B_DIM*NB*NB];        // sinkhorn result, fp16
__device__ float g_rowsum[B_DIM*NB];
__device__ int   g_kpmb[B_DIM*NB];
__device__ float g_bvo[E_DIM];              // Wo @ bv
__device__ __half g_vh[S_DIM*B_DIM*E_DIM];  // value in fp16
__device__ __half g_zh[T_DIM*B_DIM*E_DIM];  // mixed value, fp16 (rows m=t*8+b)
__device__ __half g_wvoh[E_DIM*E_DIM];      // Wo @ Wv in fp16

// =================== warp-MMA helpers (compute_80-compatible PTX) ===================
__device__ __forceinline__ uint32_t smem_u32(const void* p) {
    uint32_t a;
    asm("{ .reg .u64 t; cvta.to.shared.u64 t, %1; cvt.u32.u64 %0, t; }" : "=r"(a) : "l"(p));
    return a;
}

#define CP_ASYNC16(dst, src) \
    asm volatile("cp.async.cg.shared.global [%0], [%1], 16;" :: "r"(dst), "l"(src))
#define CP_COMMIT() asm volatile("cp.async.commit_group;")
#define CP_WAIT3()  asm volatile("cp.async.wait_group 3;")
#define CP_WAIT1()  asm volatile("cp.async.wait_group 1;")
#define CP_WAIT0()  asm volatile("cp.async.wait_group 0;")

#define LDSM_X4(r0, r1, r2, r3, addr) \
    asm volatile("ldmatrix.sync.aligned.m8n8.x4.shared.b16 {%0,%1,%2,%3}, [%4];" \
        : "=r"(r0), "=r"(r1), "=r"(r2), "=r"(r3) : "r"(addr))

#define LDSM_X4_T(r0, r1, r2, r3, addr) \
    asm volatile("ldmatrix.sync.aligned.m8n8.x4.trans.shared.b16 {%0,%1,%2,%3}, [%4];" \
        : "=r"(r0), "=r"(r1), "=r"(r2), "=r"(r3) : "r"(addr))

#define MMA16816F16(d, a0, a1, a2, a3, b0, b1) \
    asm volatile("mma.sync.aligned.m16n8k16.row.col.f32.f16.f16.f32 " \
        "{%0,%1,%2,%3}, {%4,%5,%6,%7}, {%8,%9}, {%0,%1,%2,%3};" \
        : "+f"((d)[0]), "+f"((d)[1]), "+f"((d)[2]), "+f"((d)[3]) \
        : "r"(a0), "r"(a1), "r"(a2), "r"(a3), "r"(b0), "r"(b1))

// =================== generic fp16 HMMA GEMM ===================
// C[m,n] = alpha * sum_k A[m,k]*B'[n,k]  (+bias[n])
// BTRANS=false: B row-major (N,K); BTRANS=true: B row-major (K,N)
// CTA 128x128, warps 2(m)x4(n), warp tile 64x32, KC=32, double buffer.
#define HG_A_ROW 80
#define HG_A_TILE (128*HG_A_ROW)   // 10240
#define HG_BT_ROW 272
#define HG_BT_TILE (32*HG_BT_ROW)  // 8704

template <bool BTRANS, bool BIAS, bool OUT_HALF>
__global__ __launch_bounds__(256)
void hgemm_kernel(void* __restrict__ Cv, const __half* __restrict__ A,
                  const __half* __restrict__ B, const float* __restrict__ bias,
                  int M, int N, int K, float alpha, long sA, long sB, long sC) {
    constexpr int B_TILE = BTRANS ? HG_BT_TILE : HG_A_TILE;
    constexpr int STAGE = HG_A_TILE + B_TILE;
    extern __shared__ char smem[];
    uint32_t sbase = smem_u32(smem);

    int z = blockIdx.z;
    A += (long)z * sA; B += (long)z * sB;

    int tid = threadIdx.x, wid = tid >> 5, lane = tid & 31;
    int bm = blockIdx.y * 128, bn = blockIdx.x * 128;
    int wm = (wid & 1) * 64, wn = (wid >> 1) * 32;

    float acc[4][4][4];
#pragma unroll
    for (int i = 0; i < 4; i++)
#pragma unroll
        for (int j = 0; j < 4; j++)
#pragma unroll
            for (int r = 0; r < 4; r++) acc[i][j][r] = 0.f;

    auto stage_load = [&](int kt, int buf) {
        int k0 = kt * 32;
        uint32_t base = sbase + buf * STAGE;
#pragma unroll
        for (int q = 0; q < 2; q++) {         // A: 128x32 fp16 = 512 chunks
            int c = tid + q * 256;
            int row = c >> 2, seg = c & 3;
            CP_ASYNC16(base + row * HG_A_ROW + seg * 16,
                       A + (size_t)(bm + row) * K + k0 + seg * 8);
        }
        if (!BTRANS) {
#pragma unroll
            for (int q = 0; q < 2; q++) {     // B: 128 n-rows x 32 k
                int c = tid + q * 256;
                int row = c >> 2, seg = c & 3;
                CP_ASYNC16(base + HG_A_TILE + row * HG_A_ROW + seg * 16,
                           B + (size_t)(bn + row) * K + k0 + seg * 8);
            }
        } else {
#pragma unroll
            for (int q = 0; q < 2; q++) {     // B: 32 k-rows x 128 n
                int c = tid + q * 256;
                int kk = c >> 4, seg = c & 15;
                CP_ASYNC16(base + HG_A_TILE + kk * HG_BT_ROW + seg * 16,
                           B + (size_t)(k0 + kk) * N + bn + seg * 8);
            }
        }
        CP_COMMIT();
    };

    int lrow = lane & 15, lhi = lane >> 4;

    stage_load(0, 0);
    int NKT = K / 32;
    for (int kt = 0; kt < NKT; kt++) {
        if (kt + 1 < NKT) { stage_load(kt + 1, (kt + 1) & 1); CP_WAIT1(); }
        else CP_WAIT0();
        __syncthreads();

        uint32_t base = sbase + (kt & 1) * STAGE;
        uint32_t aS = base, bS = base + HG_A_TILE;

#pragma unroll
        for (int ks = 0; ks < 2; ks++) {
            uint32_t a[4][4], bt[2][4];
#pragma unroll
            for (int mt = 0; mt < 4; mt++) {
                uint32_t off = (wm + mt * 16 + lrow) * HG_A_ROW + (ks * 16 + lhi * 8) * 2;
                LDSM_X4(a[mt][0], a[mt][1], a[mt][2], a[mt][3], aS + off);
            }
            if (!BTRANS) {
#pragma unroll
                for (int nt = 0; nt < 2; nt++) {
                    uint32_t off = (wn + nt * 16 + lrow) * HG_A_ROW + (ks * 16 + lhi * 8) * 2;
                    LDSM_X4(bt[nt][0], bt[nt][1], bt[nt][2], bt[nt][3], bS + off);
                }
#pragma unroll
                for (int mt = 0; mt < 4; mt++)
#pragma unroll
                    for (int j = 0; j < 4; j++) {
                        int nt = j >> 1, hi = j & 1;
                        MMA16816F16(acc[mt][j], a[mt][0], a[mt][1], a[mt][2], a[mt][3],
                                    bt[nt][hi], bt[nt][hi + 2]);
                    }
            } else {
#pragma unroll
                for (int ng = 0; ng < 2; ng++) {
                    uint32_t off = (ks * 16 + lrow) * HG_BT_ROW + (wn + ng * 16 + lhi * 8) * 2;
                    LDSM_X4_T(bt[ng][0], bt[ng][1], bt[ng][2], bt[ng][3], bS + off);
                }
#pragma unroll
                for (int mt = 0; mt < 4; mt++)
#pragma unroll
                    for (int j = 0; j < 4; j++) {
                        int ng = j >> 1, hi = j & 1;
                        MMA16816F16(acc[mt][j], a[mt][0], a[mt][1], a[mt][2], a[mt][3],
                                    bt[ng][hi * 2], bt[ng][hi * 2 + 1]);
                    }
            }
        }
        __syncthreads();
    }

    // ---- epilogue ----
#pragma unroll
    for (int mt = 0; mt < 4; mt++) {
        int m0 = bm + wm + mt * 16 + (lane >> 2);
        int m1 = m0 + 8;
#pragma unroll
        for (int j = 0; j < 4; j++) {
            int n = bn + wn + j * 8 + (lane & 3) * 2;
            float v00 = acc[mt][j][0] * alpha, v01 = acc[mt][j][1] * alpha;
            float v10 = acc[mt][j][2] * alpha, v11 = acc[mt][j][3] * alpha;
            if (BIAS) {
                float b0 = bias[n], b1 = bias[n + 1];
                v00 += b0; v01 += b1; v10 += b0; v11 += b1;
            }
            if (OUT_HALF) {
                __half* C = (__half*)Cv + (long)z * sC;
                *(__half2*)(C + (size_t)m0 * N + n) = __floats2half2_rn(v00, v01);
                *(__half2*)(C + (size_t)m1 * N + n) = __floats2half2_rn(v10, v11);
            } else {
                float* C = (float*)Cv + (long)z * sC;
                *(float2*)(C + (size_t)m0 * N + n) = make_float2(v00, v01);
                *(float2*)(C + (size_t)m1 * N + n) = make_float2(v10, v11);
            }
        }
    }
}

// =================== final GEMM: out = Zh*Wh' + bo + rowsum*bvo ===================
#define KC 32
#define ROW_B 80
#define A_TILE_B (128*ROW_B)
#define B_TILE_B (256*ROW_B)
#define STAGE_B (A_TILE_B + B_TILE_B)
#define HMMA_SMEM (4*STAGE_B)

__global__ __launch_bounds__(256, 1)
void hmma_out_kernel(float* __restrict__ out,
                     const __half* __restrict__ Ah, const __half* __restrict__ Bh,
                     const float* __restrict__ bo, const float* __restrict__ bvo,
                     const float* __restrict__ rowsum) {
    extern __shared__ char smem[];
    uint32_t sbase = smem_u32(smem);

    int tid = threadIdx.x, wid = tid >> 5, lane = tid & 31;
    int bm = blockIdx.y * 128, bn = blockIdx.x * 256;
    int wm = (wid & 1) * 64, wn = (wid >> 1) * 64;

    const __half* Ag = Ah + (size_t)bm * 1024;
    const __half* Bg = Bh + (size_t)bn * 1024;

    float acc[4][8][4];
#pragma unroll
    for (int i = 0; i < 4; i++)
#pragma unroll
        for (int j = 0; j < 8; j++)
#pragma unroll
            for (int r = 0; r < 4; r++) acc[i][j][r] = 0.f;

    auto stage_load = [&](int kt, int buf) {
        int k0 = kt * KC;
        uint32_t base = sbase + buf * STAGE_B;
#pragma unroll
        for (int q = 0; q < 2; q++) {
            int c = tid + q * 256;
            int row = c >> 2, seg = c & 3;
            CP_ASYNC16(base + row * ROW_B + seg * 16,
                       Ag + (size_t)row * 1024 + k0 + seg * 8);
        }
#pragma unroll
        for (int q = 0; q < 4; q++) {
            int c = tid + q * 256;
            int row = c >> 2, seg = c & 3;
            CP_ASYNC16(base + A_TILE_B + row * ROW_B + seg * 16,
                       Bg + (size_t)row * 1024 + k0 + seg * 8);
        }
    };

    int lrow = lane & 15, lkseg = (lane >> 4) * 8;

    stage_load(0, 0); CP_COMMIT();
    stage_load(1, 1); CP_COMMIT();
    stage_load(2, 2); CP_COMMIT();

    const int NKT = 1024 / KC;
    for (int kt = 0; kt < NKT; kt++) {
        if (kt + 3 < NKT) stage_load(kt + 3, (kt + 3) & 3);
        CP_COMMIT();
        CP_WAIT3();
        __syncthreads();

        uint32_t base = sbase + (kt & 3) * STAGE_B;
        uint32_t aS = base, bS = base + A_TILE_B;

#pragma unroll
        for (int ks = 0; ks < KC / 16; ks++) {
            int kb = (ks * 16 + lkseg) * 2;
            uint32_t a[4][4], b[4][4];
#pragma unroll
            for (int mt = 0; mt < 4; mt++) {
                uint32_t off = (wm + mt * 16 + lrow) * ROW_B + kb;
                LDSM_X4(a[mt][0], a[mt][1], a[mt][2], a[mt][3], aS + off);
            }
#pragma unroll
            for (int nt = 0; nt < 4; nt++) {
                uint32_t off = (wn + nt * 16 + lrow) * ROW_B + kb;
                LDSM_X4(b[nt][0], b[nt][1], b[nt][2], b[nt][3], bS + off);
            }
#pragma unroll
            for (int mt = 0; mt < 4; mt++) {
#pragma unroll
                for (int j = 0; j < 8; j++) {
                    int nt = j >> 1, hi = j & 1;
                    MMA16816F16(acc[mt][j], a[mt][0], a[mt][1], a[mt][2], a[mt][3],
                                b[nt][hi], b[nt][hi + 2]);
                }
            }
        }
        __syncthreads();
    }

#pragma unroll
    for (int mt = 0; mt < 4; mt++) {
        int m0 = bm + wm + mt * 16 + (lane >> 2);
        int m1 = m0 + 8;
        float rs0 = rowsum[((m0 & 7) << 8) | (m0 >> 7)];
        float rs1 = rowsum[((m1 & 7) << 8) | (m1 >> 7)];
#pragma unroll
        for (int j = 0; j < 8; j++) {
            int n = bn + wn + j * 8 + (lane & 3) * 2;
            float b0 = bo[n], b1 = bo[n + 1], v0 = bvo[n], v1 = bvo[n + 1];
            *(float2*)(out + (size_t)m0 * 1024 + n) =
                make_float2(acc[mt][j][0] + b0 + rs0 * v0, acc[mt][j][1] + b1 + rs0 * v1);
            *(float2*)(out + (size_t)m1 * 1024 + n) =
                make_float2(acc[mt][j][2] + b0 + rs1 * v0, acc[mt][j][3] + b1 + rs1 * v1);
        }
    }
}

// =================== zmix as fp16 warp-MMA ===================
#define ZA_ROW_B 80
#define ZA_TILE_B (128*ZA_ROW_B)
#define ZB_ROW_B 272
#define ZB_TILE_B (32*ZB_ROW_B)
#define ZSTAGE_B (ZA_TILE_B + ZB_TILE_B)
#define ZSMEM (2*ZSTAGE_B)

__global__ __launch_bounds__(256, 1)
void zmix_hmma_kernel(const __half* __restrict__ Ph, const __half* __restrict__ Vh,
                      __half* __restrict__ Zh) {
    extern __shared__ char smem[];
    uint32_t sbase = smem_u32(smem);

    int tid = threadIdx.x, wid = tid >> 5, lane = tid & 31;
    int b = blockIdx.z;
    int pos = blockIdx.y >> 1, mt0 = blockIdx.y & 1;
    int bm = mt0 * 128, bn = blockIdx.x * 128;
    int wm = (wid & 1) * 64, wn = (wid >> 1) * 32;

    const __half* Ag = Ph + (size_t)b * (NB * NB) + (size_t)bm * 256;

    float acc[4][4][4];
#pragma unroll
    for (int i = 0; i < 4; i++)
#pragma unroll
        for (int j = 0; j < 4; j++)
#pragma unroll
            for (int r = 0; r < 4; r++) acc[i][j][r] = 0.f;

    auto stage_load = [&](int kt, int buf) {
        int k0 = kt * 32;
        uint32_t base = sbase + buf * ZSTAGE_B;
#pragma unroll
        for (int q = 0; q < 2; q++) {
            int c = tid + q * 256;
            int row = c >> 2, seg = c & 3;
            CP_ASYNC16(base + row * ZA_ROW_B + seg * 16,
                       Ag + (size_t)row * 256 + k0 + seg * 8);
        }
#pragma unroll
        for (int q = 0; q < 2; q++) {
            int c = tid + q * 256;
            int kk = c >> 4, seg = c & 15;
            size_t grow = (size_t)(16 * (k0 + kk) + pos) * (B_DIM * E_DIM) + b * E_DIM + bn;
            CP_ASYNC16(base + ZA_TILE_B + kk * ZB_ROW_B + seg * 16, Vh + grow + seg * 8);
        }
        CP_COMMIT();
    };

    int lrow = lane & 15, lhi = lane >> 4;

    stage_load(0, 0);
    for (int kt = 0; kt < 8; kt++) {
        if (kt + 1 < 8) { stage_load(kt + 1, (kt + 1) & 1); CP_WAIT1(); }
        else CP_WAIT0();
        __syncthreads();

        uint32_t base = sbase + (kt & 1) * ZSTAGE_B;
        uint32_t aS = base, bS = base + ZA_TILE_B;

#pragma unroll
        for (int ks = 0; ks < 2; ks++) {
            uint32_t a[4][4], bt[2][4];
#pragma unroll
            for (int mt = 0; mt < 4; mt++) {
                uint32_t off = (wm + mt * 16 + lrow) * ZA_ROW_B + (ks * 16 + lhi * 8) * 2;
                LDSM_X4(a[mt][0], a[mt][1], a[mt][2], a[mt][3], aS + off);
            }
#pragma unroll
            for (int ng = 0; ng < 2; ng++) {
                uint32_t off = (ks * 16 + lrow) * ZB_ROW_B + (wn + ng * 16 + lhi * 8) * 2;
                LDSM_X4_T(bt[ng][0], bt[ng][1], bt[ng][2], bt[ng][3], bS + off);
            }
#pragma unroll
            for (int mt = 0; mt < 4; mt++) {
#pragma unroll
                for (int j = 0; j < 4; j++) {
                    int ng = j >> 1, hi = j & 1;
                    MMA16816F16(acc[mt][j], a[mt][0], a[mt][1], a[mt][2], a[mt][3],
                                bt[ng][hi * 2], bt[ng][hi * 2 + 1]);
                }
            }
        }
        __syncthreads();
    }

#pragma unroll
    for (int mt = 0; mt < 4; mt++) {
        int tb0 = bm + wm + mt * 16 + (lane >> 2);
        int tb1 = tb0 + 8;
        size_t r0 = ((size_t)(tb0 * 16 + pos) * 8 + b) * 1024;
        size_t r1 = ((size_t)(tb1 * 16 + pos) * 8 + b) * 1024;
#pragma unroll
        for (int j = 0; j < 4; j++) {
            int e = bn + wn + j * 8 + (lane & 3) * 2;
            *(__half2*)(Zh + r0 + e) = __floats2half2_rn(acc[mt][j][0], acc[mt][j][1]);
            *(__half2*)(Zh + r1 + e) = __floats2half2_rn(acc[mt][j][2], acc[mt][j][3]);
        }
    }
}

// =================== elementwise / small kernels ===================
__global__ void bucket_mean_h_kernel(const float* __restrict__ X, __half* __restrict__ out) {
    int o = blockIdx.x * 256 + threadIdx.x;
    int e = o & (E_DIM - 1);
    int m = o >> 10;
    int b = m >> 8;
    int i = m & 255;
    const float* src = X + (size_t)(i * BUCKET) * (B_DIM * E_DIM) + b * E_DIM + e;
    float s = 0.f;
#pragma unroll
    for (int pos = 0; pos < BUCKET; pos++) s += src[(size_t)pos * (B_DIM * E_DIM)];
    out[o] = __float2half_rn(s * (1.0f / BUCKET));
}

__global__ void kpmb_kernel(const unsigned char* __restrict__ mask, int* __restrict__ kpmb) {
    int j = blockIdx.x * 256 + threadIdx.x;
    if (j >= B_DIM * NB) return;
    int b = j >> 8, s = j & 255;
    const unsigned char* m = mask + b * S_DIM + s * BUCKET;
    int all = 1;
#pragma unroll
    for (int t = 0; t < BUCKET; t++) all &= (m[t] != 0);
    kpmb[j] = all;
}

__global__ void mask_kernel(float* __restrict__ la, const int* __restrict__ kpmb) {
    int idx = blockIdx.x * 256 + threadIdx.x;
    int b = idx >> 16, i = (idx >> 8) & 255, j = idx & 255;
    if (kpmb[b * 256 + i] != kpmb[b * 256 + j]) la[idx] = -1e30f;
}

__global__ void bvo_kernel(const float* __restrict__ Wo, const float* __restrict__ bv,
                           float* __restrict__ bvo) {
    int g = blockIdx.x * 8 + (threadIdx.x >> 5);
    int l = threadIdx.x & 31;
    if (g >= E_DIM) return;
    float s = 0.f;
    for (int k = l; k < E_DIM; k += 32) s += Wo[(size_t)g * E_DIM + k] * bv[k];
#pragma unroll
    for (int off = 16; off; off >>= 1) s += __shfl_xor_sync(0xffffffffu, s, off);
    if (l == 0) bvo[g] = s;
}

// vectorized fp32 -> fp16 (8 elements / thread); n multiple of 2048
__global__ void cvt8_kernel(const float* __restrict__ X, __half* __restrict__ H) {
    size_t i = ((size_t)blockIdx.x * 256 + threadIdx.x) * 8;
    float4 a = *(const float4*)(X + i);
    float4 c = *(const float4*)(X + i + 4);
    __half2 h[4];
    h[0] = __floats2half2_rn(a.x, a.y);
    h[1] = __floats2half2_rn(a.z, a.w);
    h[2] = __floats2half2_rn(c.x, c.y);
    h[3] = __floats2half2_rn(c.z, c.w);
    *(uint4*)(H + i) = *(uint4*)h;
}

// ---------------- fused sinkhorn: one read+write pass per iteration ----------------
__global__ __launch_bounds__(1024, 1)
void sinkhorn_kernel(float* __restrict__ la, __half* __restrict__ ph, float* __restrict__ rowsum) {
    int b = blockIdx.x;
    float* base = la + b * (NB * NB);
    int tid = threadIdx.x, w = tid >> 5, l = tid & 31;
    __shared__ float sh[32 * 256];
    __shared__ float colv[256];
    if (tid < 256) colv[tid] = 0.f;
    __syncthreads();

    for (int it = 0; it < 8; it++) {
        float cv[8], cs[8];
#pragma unroll
        for (int ci = 0; ci < 8; ci++) { cv[ci] = colv[ci * 32 + l]; cs[ci] = 0.f; }
#pragma unroll
        for (int ri = 0; ri < 8; ri++) {
            int r = w * 8 + ri;
            float v[8];
#pragma unroll
            for (int ci = 0; ci < 8; ci++) v[ci] = base[r * 256 + ci * 32 + l] - cv[ci];
            float m = v[0];
#pragma unroll
            for (int ci = 1; ci < 8; ci++) m = fmaxf(m, v[ci]);
#pragma unroll
            for (int off = 16; off; off >>= 1) m = fmaxf(m, __shfl_xor_sync(0xffffffffu, m, off));
            float s = 0.f;
#pragma unroll
            for (int ci = 0; ci < 8; ci++) s += __expf(v[ci] - m);
#pragma unroll
            for (int off = 16; off; off >>= 1) s += __shfl_xor_sync(0xffffffffu, s, off);
            float lse = m + __logf(s);
#pragma unroll
            for (int ci = 0; ci < 8; ci++) {
                float wv = v[ci] - lse;
                base[r * 256 + ci * 32 + l] = wv;
                cs[ci] += __expf(wv);
            }
        }
#pragma unroll
        for (int ci = 0; ci < 8; ci++) sh[w * 256 + ci * 32 + l] = cs[ci];
        __syncthreads();
        if (tid < 256) {
            float s = 0.f;
#pragma unroll 4
            for (int ww = 0; ww < 32; ww++) s += sh[ww * 256 + tid];
            colv[tid] = __logf(s);
        }
        __syncthreads();
    }

    float cv[8];
#pragma unroll
    for (int ci = 0; ci < 8; ci++) cv[ci] = colv[ci * 32 + l];
#pragma unroll
    for (int ri = 0; ri < 8; ri++) {
        int r = w * 8 + ri;
        float s = 0.f;
#pragma unroll
        for (int ci = 0; ci < 8; ci++) {
            float e = __expf(base[r * 256 + ci * 32 + l] - cv[ci]);
            ph[b * (NB * NB) + r * 256 + ci * 32 + l] = __float2half_rn(e);
            s += e;
        }
#pragma unroll
        for (int off = 16; off; off >>= 1) s += __shfl_xor_sync(0xffffffffu, s, off);
        if (l == 0) rowsum[b * 256 + r] = s;
    }
}

// ---------------- launch ----------------
extern "C" void kernel_launch(void* const* d_in, const int* in_sizes, int n_in,
                              void* d_out, int out_size) {
    const float* query = (const float*)d_in[0];
    const float* key_t = (const float*)d_in[1];
    const float* value = (const float*)d_in[2];
    const unsigned char* kpm = (const unsigned char*)d_in[3];
    const float* Wq = (const float*)d_in[4];
    const float* bq = (const float*)d_in[5];
    const float* Wk = (const float*)d_in[6];
    const float* bk = (const float*)d_in[7];
    const float* Wv = (const float*)d_in[8];
    const float* bv = (const float*)d_in[9];
    const float* Wo = (const float*)d_in[10];
    const float* bo = (const float*)d_in[11];
    float* out = (float*)d_out;

    float *la, *rowsum, *bvo;
    __half *qmh, *kmh, *qbh, *kbh, *Wqh, *Wkh, *Wvh, *Woh, *ph, *vh, *zh, *wvoh;
    int* kpmb;
    cudaGetSymbolAddress((void**)&qmh, g_qmh);
    cudaGetSymbolAddress((void**)&kmh, g_kmh);
    cudaGetSymbolAddress((void**)&qbh, g_qbh);
    cudaGetSymbolAddress((void**)&kbh, g_kbh);
    cudaGetSymbolAddress((void**)&Wqh, g_Wqh);
    cudaGetSymbolAddress((void**)&Wkh, g_Wkh);
    cudaGetSymbolAddress((void**)&Wvh, g_Wvh);
    cudaGetSymbolAddress((void**)&Woh, g_Woh);
    cudaGetSymbolAddress((void**)&la, g_la);
    cudaGetSymbolAddress((void**)&ph, g_ph);
    cudaGetSymbolAddress((void**)&rowsum, g_rowsum);
    cudaGetSymbolAddress((void**)&kpmb, g_kpmb);
    cudaGetSymbolAddress((void**)&bvo, g_bvo);
    cudaGetSymbolAddress((void**)&vh, g_vh);
    cudaGetSymbolAddress((void**)&zh, g_zh);
    cudaGetSymbolAddress((void**)&wvoh, g_wvoh);

    static bool attr_set = false;
    if (!attr_set) {
        cudaFuncSetAttribute(hmma_out_kernel, cudaFuncAttributeMaxDynamicSharedMemorySize, HMMA_SMEM);
        attr_set = true;
    }

    const int HG_SMEM_N = 2 * (HG_A_TILE + HG_A_TILE);   // 40960
    const int HG_SMEM_T = 2 * (HG_A_TILE + HG_BT_TILE);  // 37888

    // 0) conversions
    cvt8_kernel<<<(S_DIM * B_DIM * E_DIM) / 2048, 256>>>(value, vh);
    cvt8_kernel<<<(E_DIM * E_DIM) / 2048, 256>>>(Wq, Wqh);
    cvt8_kernel<<<(E_DIM * E_DIM) / 2048, 256>>>(Wk, Wkh);
    cvt8_kernel<<<(E_DIM * E_DIM) / 2048, 256>>>(Wv, Wvh);
    cvt8_kernel<<<(E_DIM * E_DIM) / 2048, 256>>>(Wo, Woh);

    // 1) bucket means -> fp16
    bucket_mean_h_kernel<<<(B_DIM * NB * E_DIM) / 256, 256>>>(query, qmh);
    bucket_mean_h_kernel<<<(B_DIM * NB * E_DIM) / 256, 256>>>(key_t, kmh);

    // 2) project bucket means (fp16 HMMA): qb = qm @ Wq^T + bq
    hgemm_kernel<false, true, true><<<dim3(8, 16, 1), 256, HG_SMEM_N>>>(
        qbh, qmh, Wqh, bq, 2048, 1024, 1024, 1.0f, 0, 0, 0);
    hgemm_kernel<false, true, true><<<dim3(8, 16, 1), 256, HG_SMEM_N>>>(
        kbh, kmh, Wkh, bk, 2048, 1024, 1024, 1.0f, 0, 0, 0);

    // 3) wvo = Wo @ Wv (B trans), fp16 out; bvo = Wo @ bv (fp32)
    hgemm_kernel<true, false, true><<<dim3(8, 8, 1), 256, HG_SMEM_T>>>(
        wvoh, Woh, Wvh, nullptr, 1024, 1024, 1024, 1.0f, 0, 0, 0);
    bvo_kernel<<<128, 256>>>(Wo, bv, bvo);

    // 4) attn logits (fp16 HMMA, fp32 out with alpha), batched over B
    hgemm_kernel<false, false, false><<<dim3(2, 2, B_DIM), 256, HG_SMEM_N>>>(
        la, qbh, kbh, nullptr, 256, 256, 1024, ATTN_ALPHA,
        (long)NB * E_DIM, (long)NB * E_DIM, (long)NB * NB);

    // 5) mask
    kpmb_kernel<<<8, 256>>>(kpm, kpmb);
    mask_kernel<<<(B_DIM * NB * NB) / 256, 256>>>(la, kpmb);

    // 6) sinkhorn -> ph (fp16), rowsum
    sinkhorn_kernel<<<B_DIM, 1024>>>(la, ph, rowsum);

    // 7) bucket mix via fp16 MMA -> zh
    zmix_hmma_kernel<<<dim3(8, 32, 8), 256, ZSMEM>>>(ph, vh, zh);

    // 8) final: fp16 warp-MMA GEMM (M=32768, N=1024, K=1024)
    hmma_out_kernel<<<dim3(4, 256, 1), 256, HMMA_SMEM>>>(
        out, zh, wvoh, bo, bvo, rowsum);
}